// round 12
// baseline (speedup 1.0000x reference)
#include <cuda_runtime.h>
#include <cuda_fp16.h>
#include <cstdint>

#define DIMSZ 512
#define NHEAD 8
#define HDIM  64
#define NB    4096
#define BSZ   32
#define SQ    128
#define BSROWS 4096
#define EPSLN 1e-5f

// scratch (allocation-free rule: __device__ globals)
__device__ __half g_xh[3 * BSROWS * DIMSZ];   // x_q, x_k, x_v in fp16
__device__ __half g_wh[4 * DIMSZ * DIMSZ];    // Wq, Wk, Wv, Wproj in fp16
__device__ float  g_Q[BSROWS * DIMSZ];
__device__ __half g_K[NB * DIMSZ];
__device__ __half g_V[NB * DIMSZ];
__device__ float  g_X[BSROWS * DIMSZ];
__device__ __half g_Xh[BSROWS * DIMSZ];

// ---------------------------------------------------------------------------
// helpers
// ---------------------------------------------------------------------------
__device__ __forceinline__ unsigned tf32_of(float f) {
    unsigned u;
    asm("cvt.rna.tf32.f32 %0, %1;" : "=r"(u) : "f"(f));
    return u;
}
__device__ __forceinline__ float tf32f(float f) {
    return __uint_as_float(tf32_of(f));
}
__device__ __forceinline__ void mma_f16(
    float& c0, float& c1, float& c2, float& c3,
    unsigned a0, unsigned a1, unsigned a2, unsigned a3,
    unsigned b0, unsigned b1)
{
    asm volatile(
        "mma.sync.aligned.m16n8k16.row.col.f32.f16.f16.f32 "
        "{%0,%1,%2,%3}, {%4,%5,%6,%7}, {%8,%9}, {%0,%1,%2,%3};"
        : "+f"(c0), "+f"(c1), "+f"(c2), "+f"(c3)
        : "r"(a0), "r"(a1), "r"(a2), "r"(a3), "r"(b0), "r"(b1));
}
__device__ __forceinline__ unsigned f16x2_of(float lo, float hi) {
    unsigned d;
    asm("cvt.rn.f16x2.f32 %0, %1, %2;" : "=r"(d) : "f"(hi), "f"(lo));
    return d;
}
__device__ __forceinline__ void ldsm4(
    unsigned& r0, unsigned& r1, unsigned& r2, unsigned& r3, uint32_t addr)
{
    asm volatile(
        "ldmatrix.sync.aligned.m8n8.x4.shared.b16 {%0,%1,%2,%3}, [%4];"
        : "=r"(r0), "=r"(r1), "=r"(r2), "=r"(r3) : "r"(addr));
}
__device__ __forceinline__ void ldsm4t(
    unsigned& r0, unsigned& r1, unsigned& r2, unsigned& r3, uint32_t addr)
{
    asm volatile(
        "ldmatrix.sync.aligned.m8n8.x4.trans.shared.b16 {%0,%1,%2,%3}, [%4];"
        : "=r"(r0), "=r"(r1), "=r"(r2), "=r"(r3) : "r"(addr));
}
__device__ __forceinline__ void cpa16(uint32_t s, const void* g) {
    asm volatile("cp.async.cg.shared.global [%0], [%1], 16;" :: "r"(s), "l"(g));
}
__device__ __forceinline__ void cpa_commit() { asm volatile("cp.async.commit_group;"); }
__device__ __forceinline__ void cpa_wait1()  { asm volatile("cp.async.wait_group 1;"); }
__device__ __forceinline__ void cpa_wait0()  { asm volatile("cp.async.wait_group 0;"); }

// ---------------------------------------------------------------------------
// fp32 -> fp16 conversion pass for x_q/x_k/x_v (z=0..2) and W's (z=3..6)
// ---------------------------------------------------------------------------
__global__ __launch_bounds__(256) void cvt_f2h(
    const float* __restrict__ x_q, const float* __restrict__ x_k,
    const float* __restrict__ x_v,
    const float* __restrict__ Wq, const float* __restrict__ Wk,
    const float* __restrict__ Wv, const float* __restrict__ Wp,
    __half* __restrict__ xh, __half* __restrict__ wh)
{
    int z = blockIdx.y;
    const float* s;
    __half* d;
    int n;
    if (z < 3) {
        s = (z == 0) ? x_q : (z == 1) ? x_k : x_v;
        d = xh + (size_t)z * BSROWS * DIMSZ;
        n = BSROWS * DIMSZ;
    } else {
        int zz = z - 3;
        s = (zz == 0) ? Wq : (zz == 1) ? Wk : (zz == 2) ? Wv : Wp;
        d = wh + (size_t)zz * DIMSZ * DIMSZ;
        n = DIMSZ * DIMSZ;
    }
    int idx = (blockIdx.x * 256 + threadIdx.x) * 8;
    if (idx >= n) return;
    float4 a = *(const float4*)(s + idx);
    float4 b = *(const float4*)(s + idx + 4);
    *(uint4*)(d + idx) = make_uint4(
        f16x2_of(a.x, a.y), f16x2_of(a.z, a.w),
        f16x2_of(b.x, b.y), f16x2_of(b.z, b.w));
}

// ---------------------------------------------------------------------------
// fp16 GEMM (fp32 accumulate), 2-stage cp.async pipeline. (unchanged, R10)
// ---------------------------------------------------------------------------
#define GHS 72
#define ABUF (128 * GHS)
#define BBUF (64 * GHS)
#define GEMM_SMEM ((2 * ABUF + 2 * BBUF) * 2)

__device__ __forceinline__ void gemm_body(
    const __half* __restrict__ A, const __half* __restrict__ Bw,
    float* __restrict__ C, __half* __restrict__ Ch,
    int bm, int bn, int mode,
    const float* __restrict__ lng, const float* __restrict__ lnb, float lscale)
{
    extern __shared__ __half gsmh[];   // [A0][A1][B0][B1]
    float* red = (float*)gsmh;
    const uint32_t smem_u = (uint32_t)__cvta_generic_to_shared(gsmh);

    const int tid = threadIdx.x;
    const int lane = tid & 31, w = tid >> 5;
    const int q4 = lane & 3, r4 = lane >> 2;
    const int wm = (w & 3) * 32;
    const int wn = (w >> 2);
    const int wncol = wn * 32;

    const int arow[4] = { (tid + 0) >> 3, (tid + 256) >> 3, (tid + 512) >> 3, (tid + 768) >> 3 };
    const int brow[2] = { (tid + 0) >> 3, (tid + 256) >> 3 };
    const int hg = (tid & 7) * 8;

    const int lm_mat = lane >> 3, lm_r = lane & 7;
    const uint32_t alm_off =
        (uint32_t)(((wm + (lm_mat & 1) * 8 + lm_r) * GHS) + (lm_mat >> 1) * 8) * 2;
    const uint32_t blm_off = (uint32_t)(2 * ABUF) * 2 +
        (uint32_t)(((wncol + (lm_mat >> 1) * 8 + lm_r) * GHS) + (lm_mat & 1) * 8) * 2;

#pragma unroll
    for (int i = 0; i < 4; i++)
        cpa16(smem_u + (uint32_t)(arow[i] * GHS + hg) * 2,
              A + (size_t)(bm + arow[i]) * DIMSZ + hg);
#pragma unroll
    for (int i = 0; i < 2; i++)
        cpa16(smem_u + (uint32_t)(2 * ABUF + brow[i] * GHS + hg) * 2,
              Bw + (size_t)(bn + brow[i]) * DIMSZ + hg);
    cpa_commit();

    float acc[2][4][4];
#pragma unroll
    for (int mt = 0; mt < 2; mt++)
#pragma unroll
        for (int nt = 0; nt < 4; nt++)
#pragma unroll
            for (int c = 0; c < 4; c++) acc[mt][nt][c] = 0.f;

    for (int t = 0; t < 8; t++) {
        int st = t & 1;
        if (t < 7) {
            int kt = (t + 1) * 64;
            int ns = st ^ 1;
#pragma unroll
            for (int i = 0; i < 4; i++)
                cpa16(smem_u + (uint32_t)(ns * ABUF + arow[i] * GHS + hg) * 2,
                      A + (size_t)(bm + arow[i]) * DIMSZ + kt + hg);
#pragma unroll
            for (int i = 0; i < 2; i++)
                cpa16(smem_u + (uint32_t)(2 * ABUF + ns * BBUF + brow[i] * GHS + hg) * 2,
                      Bw + (size_t)(bn + brow[i]) * DIMSZ + kt + hg);
            cpa_commit();
            cpa_wait1();
        } else {
            cpa_wait0();
        }
        __syncthreads();

        const uint32_t abase = alm_off + (uint32_t)(st * ABUF) * 2 + smem_u;
        const uint32_t bbase = blm_off + (uint32_t)(st * BBUF) * 2 + smem_u;
#pragma unroll
        for (int kk = 0; kk < 4; kk++) {
            unsigned af[2][4];
#pragma unroll
            for (int mt = 0; mt < 2; mt++)
                ldsm4(af[mt][0], af[mt][1], af[mt][2], af[mt][3],
                      abase + (uint32_t)(mt * 16 * GHS + kk * 16) * 2);
#pragma unroll
            for (int nt2 = 0; nt2 < 2; nt2++) {
                unsigned b0, b1, b2, b3;
                ldsm4(b0, b1, b2, b3,
                      bbase + (uint32_t)(nt2 * 16 * GHS + kk * 16) * 2);
#pragma unroll
                for (int mt = 0; mt < 2; mt++) {
                    mma_f16(acc[mt][2 * nt2][0], acc[mt][2 * nt2][1],
                            acc[mt][2 * nt2][2], acc[mt][2 * nt2][3],
                            af[mt][0], af[mt][1], af[mt][2], af[mt][3], b0, b1);
                    mma_f16(acc[mt][2 * nt2 + 1][0], acc[mt][2 * nt2 + 1][1],
                            acc[mt][2 * nt2 + 1][2], acc[mt][2 * nt2 + 1][3],
                            af[mt][0], af[mt][1], af[mt][2], af[mt][3], b2, b3);
                }
            }
        }
        __syncthreads();
    }

    if (mode == 1 || mode == 3) {
#pragma unroll
        for (int mt = 0; mt < 2; mt++) {
#pragma unroll
            for (int half = 0; half < 2; half++) {
                float s = 0.f, ss = 0.f;
#pragma unroll
                for (int nt = 0; nt < 4; nt++) {
                    float v0 = acc[mt][nt][2 * half];
                    float v1 = acc[mt][nt][2 * half + 1];
                    s += v0 + v1;
                    ss += v0 * v0 + v1 * v1;
                }
                s += __shfl_xor_sync(0xffffffffu, s, 1);
                s += __shfl_xor_sync(0xffffffffu, s, 2);
                ss += __shfl_xor_sync(0xffffffffu, ss, 1);
                ss += __shfl_xor_sync(0xffffffffu, ss, 2);
                if (q4 == 0) {
                    int row = wm + mt * 16 + half * 8 + r4;
                    red[(wn * 128 + row) * 2 + 0] = s;
                    red[(wn * 128 + row) * 2 + 1] = ss;
                }
            }
        }
        __syncthreads();
#pragma unroll
        for (int mt = 0; mt < 2; mt++) {
#pragma unroll
            for (int half = 0; half < 2; half++) {
                int row = wm + mt * 16 + half * 8 + r4;
                float S  = red[row * 2 + 0] + red[(128 + row) * 2 + 0];
                float SS = red[row * 2 + 1] + red[(128 + row) * 2 + 1];
                float m = S * (1.f / 64.f);
                float var = SS * (1.f / 64.f) - m * m;
                float rr = rsqrtf(var + EPSLN);
#pragma unroll
                for (int nt = 0; nt < 4; nt++) {
                    int ci = wncol + nt * 8 + 2 * q4;
                    float o0 = ((acc[mt][nt][2 * half]     - m) * rr * lng[ci]     + lnb[ci])     * lscale;
                    float o1 = ((acc[mt][nt][2 * half + 1] - m) * rr * lng[ci + 1] + lnb[ci + 1]) * lscale;
                    if (mode == 1) {
                        float* cp = C + (size_t)(bm + row) * DIMSZ + bn + ci;
                        *(float2*)cp = make_float2(tf32f(o0), tf32f(o1));
                    } else {
                        __half* cp = Ch + (size_t)(bm + row) * DIMSZ + bn + ci;
                        *(__half2*)cp = __floats2half2_rn(o0, o1);
                    }
                }
            }
        }
    } else if (mode == 2) {
#pragma unroll
        for (int mt = 0; mt < 2; mt++) {
            int r0 = bm + wm + mt * 16 + r4;
#pragma unroll
            for (int nt = 0; nt < 4; nt++) {
                __half* cp = Ch + (size_t)r0 * DIMSZ + bn + wncol + nt * 8 + 2 * q4;
                *(__half2*)cp = __floats2half2_rn(acc[mt][nt][0], acc[mt][nt][1]);
                *(__half2*)(cp + (size_t)8 * DIMSZ) =
                    __floats2half2_rn(acc[mt][nt][2], acc[mt][nt][3]);
            }
        }
    } else {
#pragma unroll
        for (int mt = 0; mt < 2; mt++) {
            int r0 = bm + wm + mt * 16 + r4;
#pragma unroll
            for (int nt = 0; nt < 4; nt++) {
                float* cp = C + (size_t)r0 * DIMSZ + bn + wncol + nt * 8 + 2 * q4;
                *(float2*)cp = make_float2(acc[mt][nt][0], acc[mt][nt][1]);
                *(float2*)(cp + (size_t)8 * DIMSZ) =
                    make_float2(acc[mt][nt][2], acc[mt][nt][3]);
            }
        }
    }
}

__global__ __launch_bounds__(256, 2) void gemm_qkv(
    const __half* __restrict__ xh, const __half* __restrict__ wh,
    float* __restrict__ Qp, __half* __restrict__ Kp, __half* __restrict__ Vp,
    const float* __restrict__ qg, const float* __restrict__ qb,
    const float* __restrict__ kg, const float* __restrict__ kb)
{
    const int z = blockIdx.z;
    const __half* A  = xh + (size_t)z * BSROWS * DIMSZ;
    const __half* Bw = wh + (size_t)z * DIMSZ * DIMSZ;
    __half* Ch      = (z == 1) ? Kp : Vp;
    const float* g  = (z == 0) ? qg : kg;
    const float* bb = (z == 0) ? qb : kb;
    float sc        = (z == 0) ? 0.125f : 1.0f;
    int mode        = (z == 0) ? 1 : (z == 1) ? 3 : 2;
    gemm_body(A, Bw, Qp, Ch, blockIdx.y * 128, blockIdx.x * 64, mode, g, bb, sc);
}

__global__ __launch_bounds__(256, 2) void gemm_proj(
    const __half* __restrict__ A, const __half* __restrict__ Bw, float* __restrict__ C)
{
    gemm_body(A, Bw, C, nullptr, blockIdx.y * 128, blockIdx.x * 64, 0, nullptr, nullptr, 1.f);
}

// ---------------------------------------------------------------------------
// Full-row layernorm over D=512: fp32 in, fp16 out. One warp per row.
// ---------------------------------------------------------------------------
__global__ __launch_bounds__(256) void ln_full(
    const float* __restrict__ X, __half* __restrict__ Xh,
    const float* __restrict__ g, const float* __restrict__ bb)
{
    int row = blockIdx.x * 8 + (threadIdx.x >> 5);
    int lane = threadIdx.x & 31;
    const float* p = X + (size_t)row * DIMSZ;
    float4 x[4];
    float s = 0.f;
#pragma unroll
    for (int q = 0; q < 4; q++) {
        x[q] = *(const float4*)(p + lane * 4 + q * 128);
        s += x[q].x + x[q].y + x[q].z + x[q].w;
    }
#pragma unroll
    for (int off = 16; off; off >>= 1) s += __shfl_xor_sync(0xffffffffu, s, off);
    float m = s * (1.f / 512.f);
    float v = 0.f;
#pragma unroll
    for (int q = 0; q < 4; q++) {
        x[q].x -= m; x[q].y -= m; x[q].z -= m; x[q].w -= m;
        v += x[q].x * x[q].x + x[q].y * x[q].y + x[q].z * x[q].z + x[q].w * x[q].w;
    }
#pragma unroll
    for (int off = 16; off; off >>= 1) v += __shfl_xor_sync(0xffffffffu, v, off);
    float r = rsqrtf(v * (1.f / 512.f) + EPSLN);
#pragma unroll
    for (int q = 0; q < 4; q++) {
        int c = lane * 4 + q * 128;
        float4 gg = *(const float4*)(g + c);
        float4 bv = *(const float4*)(bb + c);
        uint2 st = make_uint2(
            f16x2_of(x[q].x * r * gg.x + bv.x, x[q].y * r * gg.y + bv.y),
            f16x2_of(x[q].z * r * gg.z + bv.z, x[q].w * r * gg.w + bv.w));
        *(uint2*)(Xh + (size_t)row * DIMSZ + c) = st;
    }
}

// ---------------------------------------------------------------------------
// Fused flash attention, fp16 operands, fixed-max softmax, cp.async
// double-buffered K/V in 128-key stages.
// 512 threads = 16 warps; warps 0-7 -> batch 2*bp, warps 8-15 -> batch 2*bp+1.
// Both batch-halves share the same smem K/V -> L2 K/V traffic halves.
// Grid = 128 blocks (batch-pair x head) = one clean wave on 148 SMs.
// ---------------------------------------------------------------------------
#define HSTR 72
#define KVS (128 * HSTR)                 // halves per stage per tensor
#define ATTN_SMEM (4 * KVS * 2)          // K0 K1 V0 V1, bytes
#define NSTG (NB / 128)                  // 32 stages
#define PEXPC 7.2134752f                 // 5.0 * log2(e)

__global__ __launch_bounds__(512, 2) void attn_mma(
    const float* __restrict__ Q, const __half* __restrict__ Kb,
    const __half* __restrict__ Vb, float* __restrict__ Xo)
{
    extern __shared__ __half asm_h[];    // [K st0][K st1][V st0][V st1]
    const uint32_t sm_u = (uint32_t)__cvta_generic_to_shared(asm_h);

    const int bph = blockIdx.x;
    const int bp = bph >> 3, h = bph & 7;
    const int tid = threadIdx.x;
    const int w = tid >> 5, lane = tid & 31;
    const int wq = w & 7, wb = w >> 3;          // query-warp slot, batch half
    const int b = bp * 2 + wb;
    const int q4 = lane & 3, r4 = lane >> 2;

    const __half* kbase = Kb + h * HDIM;
    const __half* vbase = Vb + h * HDIM;

    // fill coords: 2 chunks of 16B per tensor per thread per stage (512 thr)
    int cj[2];
    const int chg = (tid & 7) * 8;
#pragma unroll
    for (int i = 0; i < 2; i++) cj[i] = (tid + i * 512) >> 3;   // key 0..127

    const int lm_mat = lane >> 3, lm_r = lane & 7;
    const uint32_t klm_off =
        (uint32_t)(((lm_mat >> 1) * 8 + lm_r) * HSTR + (lm_mat & 1) * 8) * 2;
    const uint32_t vlm_off =
        (uint32_t)(((lm_mat & 1) * 8 + lm_r) * HSTR + (lm_mat >> 1) * 8) * 2;

    // issue stage 0
#pragma unroll
    for (int i = 0; i < 2; i++) {
        cpa16(sm_u + (uint32_t)(cj[i] * HSTR + chg) * 2,
              kbase + (size_t)cj[i] * DIMSZ + chg);
        cpa16(sm_u + (uint32_t)(2 * KVS + cj[i] * HSTR + chg) * 2,
              vbase + (size_t)cj[i] * DIMSZ + chg);
    }
    cpa_commit();

    // Q fragments: fp16, 4 k16-tiles x 4 regs
    unsigned qa[4][4];
    {
        const float* q0 = Q + (size_t)(b * SQ + wq * 16 + r4) * DIMSZ + h * HDIM;
        const float* q1 = q0 + 8 * DIMSZ;
#pragma unroll
        for (int kk = 0; kk < 4; kk++) {
            int col = kk * 16 + 2 * q4;
            qa[kk][0] = f16x2_of(q0[col],     q0[col + 1]);
            qa[kk][1] = f16x2_of(q1[col],     q1[col + 1]);
            qa[kk][2] = f16x2_of(q0[col + 8], q0[col + 9]);
            qa[kk][3] = f16x2_of(q1[col + 8], q1[col + 9]);
        }
    }

    float lA = 0.f, lB = 0.f;
    float o[8][4];
#pragma unroll
    for (int dt = 0; dt < 8; dt++)
        o[dt][0] = o[dt][1] = o[dt][2] = o[dt][3] = 0.f;

    for (int t = 0; t < NSTG; t++) {
        int st = t & 1;
        if (t + 1 < NSTG) {
            int n1 = (t + 1) * 128;
            int ns = st ^ 1;
#pragma unroll
            for (int i = 0; i < 2; i++) {
                cpa16(sm_u + (uint32_t)(ns * KVS + cj[i] * HSTR + chg) * 2,
                      kbase + (size_t)(n1 + cj[i]) * DIMSZ + chg);
                cpa16(sm_u + (uint32_t)(2 * KVS + ns * KVS + cj[i] * HSTR + chg) * 2,
                      vbase + (size_t)(n1 + cj[i]) * DIMSZ + chg);
            }
            cpa_commit();
            cpa_wait1();
        } else {
            cpa_wait0();
        }
        __syncthreads();

#pragma unroll
        for (int sub = 0; sub < 2; sub++) {
            const uint32_t kbb = sm_u + (uint32_t)(st * KVS + sub * 64 * HSTR) * 2 + klm_off;
            const uint32_t vbb = sm_u + (uint32_t)(2 * KVS + st * KVS + sub * 64 * HSTR) * 2 + vlm_off;

            // ---- scores: S = Q K^T ----
            float s[8][4];
#pragma unroll
            for (int nt = 0; nt < 8; nt++)
                s[nt][0] = s[nt][1] = s[nt][2] = s[nt][3] = 0.f;
#pragma unroll
            for (int kk = 0; kk < 4; kk++) {
#pragma unroll
                for (int nt2 = 0; nt2 < 4; nt2++) {
                    unsigned b0, b1, b2, b3;
                    ldsm4(b0, b1, b2, b3,
                          kbb + (uint32_t)(nt2 * 16 * HSTR + kk * 16) * 2);
                    mma_f16(s[2 * nt2][0], s[2 * nt2][1], s[2 * nt2][2], s[2 * nt2][3],
                            qa[kk][0], qa[kk][1], qa[kk][2], qa[kk][3], b0, b1);
                    mma_f16(s[2 * nt2 + 1][0], s[2 * nt2 + 1][1], s[2 * nt2 + 1][2], s[2 * nt2 + 1][3],
                            qa[kk][0], qa[kk][1], qa[kk][2], qa[kk][3], b2, b3);
                }
            }

            // ---- fixed-max softmax; pack P into fp16 A-fragments ----
            float suA = 0.f, suB = 0.f;
            unsigned ph[4][4];
#pragma unroll
            for (int nt = 0; nt < 8; nt++) {
                float p0 = exp2f(fmaf(s[nt][0], 1.44269504f, -PEXPC));
                float p1 = exp2f(fmaf(s[nt][1], 1.44269504f, -PEXPC));
                float p2 = exp2f(fmaf(s[nt][2], 1.44269504f, -PEXPC));
                float p3 = exp2f(fmaf(s[nt][3], 1.44269504f, -PEXPC));
                suA += p0 + p1; suB += p2 + p3;
                int tt = nt >> 1;
                if ((nt & 1) == 0) {
                    ph[tt][0] = f16x2_of(p0, p1);
                    ph[tt][1] = f16x2_of(p2, p3);
                } else {
                    ph[tt][2] = f16x2_of(p0, p1);
                    ph[tt][3] = f16x2_of(p2, p3);
                }
            }
            lA += suA;
            lB += suB;

            // ---- O += P @ V ----
#pragma unroll
            for (int kk = 0; kk < 4; kk++) {
#pragma unroll
                for (int dt2 = 0; dt2 < 4; dt2++) {
                    unsigned v0, v1, v2, v3;
                    ldsm4t(v0, v1, v2, v3,
                           vbb + (uint32_t)(kk * 16 * HSTR + dt2 * 16) * 2);
                    mma_f16(o[2 * dt2][0], o[2 * dt2][1], o[2 * dt2][2], o[2 * dt2][3],
                            ph[kk][0], ph[kk][1], ph[kk][2], ph[kk][3], v0, v1);
                    mma_f16(o[2 * dt2 + 1][0], o[2 * dt2 + 1][1], o[2 * dt2 + 1][2], o[2 * dt2 + 1][3],
                            ph[kk][0], ph[kk][1], ph[kk][2], ph[kk][3], v2, v3);
                }
            }
        }
        __syncthreads();   // all warps done reading stage before refill
    }

    lA += __shfl_xor_sync(0xffffffffu, lA, 1);
    lA += __shfl_xor_sync(0xffffffffu, lA, 2);
    lB += __shfl_xor_sync(0xffffffffu, lB, 1);
    lB += __shfl_xor_sync(0xffffffffu, lB, 2);
    float ivA = 1.f / lA, ivB = 1.f / lB;
    int rowA = b * SQ + wq * 16 + r4;
    float* xoA = Xo + (size_t)rowA * DIMSZ + h * HDIM + 2 * q4;
    float* xoB = xoA + 8 * DIMSZ;
#pragma unroll
    for (int dt = 0; dt < 8; dt++) {
        *(float2*)(xoA + dt * 8) = make_float2(o[dt][0] * ivA, o[dt][1] * ivA);
        *(float2*)(xoB + dt * 8) = make_float2(o[dt][2] * ivB, o[dt][3] * ivB);
    }
}

// ---------------------------------------------------------------------------
extern "C" void kernel_launch(void* const* d_in, const int* in_sizes, int n_in,
                              void* d_out, int out_size)
{
    const float* x_q   = (const float*)d_in[0];
    const float* x_k   = (const float*)d_in[1];
    const float* x_v   = (const float*)d_in[2];
    const float* Wq    = (const float*)d_in[3];
    const float* Wk    = (const float*)d_in[4];
    const float* Wv    = (const float*)d_in[5];
    const float* Wproj = (const float*)d_in[6];
    const float* qn_g  = (const float*)d_in[7];
    const float* qn_b  = (const float*)d_in[8];
    const float* kn_g  = (const float*)d_in[9];
    const float* kn_b  = (const float*)d_in[10];
    const float* n_g   = (const float*)d_in[11];
    const float* n_b   = (const float*)d_in[12];
    float* out = (float*)d_out;

    float *Qp, *Xp;
    __half *Kp, *Vp, *xh, *wh, *Xh;
    cudaGetSymbolAddress((void**)&Qp, g_Q);
    cudaGetSymbolAddress((void**)&Kp, g_K);
    cudaGetSymbolAddress((void**)&Vp, g_V);
    cudaGetSymbolAddress((void**)&Xp, g_X);
    cudaGetSymbolAddress((void**)&xh, g_xh);
    cudaGetSymbolAddress((void**)&wh, g_wh);
    cudaGetSymbolAddress((void**)&Xh, g_Xh);

    static bool attr_set = false;
    if (!attr_set) {
        cudaFuncSetAttribute(gemm_qkv,
                             cudaFuncAttributeMaxDynamicSharedMemorySize, GEMM_SMEM);
        cudaFuncSetAttribute(gemm_proj,
                             cudaFuncAttributeMaxDynamicSharedMemorySize, GEMM_SMEM);
        cudaFuncSetAttribute(attn_mma,
                             cudaFuncAttributeMaxDynamicSharedMemorySize, ATTN_SMEM);
        attr_set = true;
    }

    // fp32 -> fp16 inputs (x_q/x_k/x_v + 4 weights)
    dim3 cvt_grid(BSROWS * DIMSZ / (256 * 8), 7);
    cvt_f2h<<<cvt_grid, 256>>>(x_q, x_k, x_v, Wq, Wk, Wv, Wproj, xh, wh);

    // fused Q/K/V projections + per-head LN / fp16 epilogues (cp.async pipelined)
    dim3 qkv_grid(DIMSZ / 64, BSROWS / 128, 3);
    gemm_qkv<<<qkv_grid, 256, GEMM_SMEM>>>(xh, wh, Qp, Kp, Vp,
                                           qn_g, qn_b, kn_g, kn_b);

    // fused attention (fp16, fixed-max softmax, 2 batches per block)
    attn_mma<<<(BSZ / 2) * NHEAD, 512, ATTN_SMEM>>>(Qp, Kp, Vp, Xp);

    // output layernorm (fp16 out) + projection
    ln_full<<<BSROWS / 8, 256>>>(Xp, Xh, n_g, n_b);
    dim3 proj_grid(DIMSZ / 64, BSROWS / 128);
    gemm_proj<<<proj_grid, 256, GEMM_SMEM>>>(Xh, wh + 3 * DIMSZ * DIMSZ, out);
}

// round 13
// speedup vs baseline: 1.3963x; 1.3963x over previous
#include <cuda_runtime.h>
#include <cuda_fp16.h>
#include <cstdint>

#define DIMSZ 512
#define NHEAD 8
#define HDIM  64
#define NB    4096
#define BSZ   32
#define SQ    128
#define BSROWS 4096
#define EPSLN 1e-5f

// scratch (allocation-free rule: __device__ globals)
__device__ __half g_xh[3 * BSROWS * DIMSZ];   // x_q, x_k, x_v in fp16
__device__ __half g_wh[4 * DIMSZ * DIMSZ];    // Wq, Wk, Wv, Wproj in fp16
__device__ float  g_Q[BSROWS * DIMSZ];
__device__ __half g_K[NB * DIMSZ];
__device__ __half g_V[NB * DIMSZ];
__device__ float  g_X[BSROWS * DIMSZ];
__device__ __half g_Xh[BSROWS * DIMSZ];

// ---------------------------------------------------------------------------
// helpers
// ---------------------------------------------------------------------------
__device__ __forceinline__ unsigned tf32_of(float f) {
    unsigned u;
    asm("cvt.rna.tf32.f32 %0, %1;" : "=r"(u) : "f"(f));
    return u;
}
__device__ __forceinline__ float tf32f(float f) {
    return __uint_as_float(tf32_of(f));
}
__device__ __forceinline__ void mma_f16(
    float& c0, float& c1, float& c2, float& c3,
    unsigned a0, unsigned a1, unsigned a2, unsigned a3,
    unsigned b0, unsigned b1)
{
    asm volatile(
        "mma.sync.aligned.m16n8k16.row.col.f32.f16.f16.f32 "
        "{%0,%1,%2,%3}, {%4,%5,%6,%7}, {%8,%9}, {%0,%1,%2,%3};"
        : "+f"(c0), "+f"(c1), "+f"(c2), "+f"(c3)
        : "r"(a0), "r"(a1), "r"(a2), "r"(a3), "r"(b0), "r"(b1));
}
__device__ __forceinline__ unsigned f16x2_of(float lo, float hi) {
    unsigned d;
    asm("cvt.rn.f16x2.f32 %0, %1, %2;" : "=r"(d) : "f"(hi), "f"(lo));
    return d;
}
__device__ __forceinline__ void ldsm4(
    unsigned& r0, unsigned& r1, unsigned& r2, unsigned& r3, uint32_t addr)
{
    asm volatile(
        "ldmatrix.sync.aligned.m8n8.x4.shared.b16 {%0,%1,%2,%3}, [%4];"
        : "=r"(r0), "=r"(r1), "=r"(r2), "=r"(r3) : "r"(addr));
}
__device__ __forceinline__ void ldsm4t(
    unsigned& r0, unsigned& r1, unsigned& r2, unsigned& r3, uint32_t addr)
{
    asm volatile(
        "ldmatrix.sync.aligned.m8n8.x4.trans.shared.b16 {%0,%1,%2,%3}, [%4];"
        : "=r"(r0), "=r"(r1), "=r"(r2), "=r"(r3) : "r"(addr));
}
__device__ __forceinline__ void cpa16(uint32_t s, const void* g) {
    asm volatile("cp.async.cg.shared.global [%0], [%1], 16;" :: "r"(s), "l"(g));
}
__device__ __forceinline__ void cpa_commit() { asm volatile("cp.async.commit_group;"); }
__device__ __forceinline__ void cpa_wait1()  { asm volatile("cp.async.wait_group 1;"); }
__device__ __forceinline__ void cpa_wait0()  { asm volatile("cp.async.wait_group 0;"); }

// ---------------------------------------------------------------------------
// fp32 -> fp16 conversion pass for x_q/x_k/x_v (z=0..2) and W's (z=3..6)
// ---------------------------------------------------------------------------
__global__ __launch_bounds__(256) void cvt_f2h(
    const float* __restrict__ x_q, const float* __restrict__ x_k,
    const float* __restrict__ x_v,
    const float* __restrict__ Wq, const float* __restrict__ Wk,
    const float* __restrict__ Wv, const float* __restrict__ Wp,
    __half* __restrict__ xh, __half* __restrict__ wh)
{
    int z = blockIdx.y;
    const float* s;
    __half* d;
    int n;
    if (z < 3) {
        s = (z == 0) ? x_q : (z == 1) ? x_k : x_v;
        d = xh + (size_t)z * BSROWS * DIMSZ;
        n = BSROWS * DIMSZ;
    } else {
        int zz = z - 3;
        s = (zz == 0) ? Wq : (zz == 1) ? Wk : (zz == 2) ? Wv : Wp;
        d = wh + (size_t)zz * DIMSZ * DIMSZ;
        n = DIMSZ * DIMSZ;
    }
    int idx = (blockIdx.x * 256 + threadIdx.x) * 8;
    if (idx >= n) return;
    float4 a = *(const float4*)(s + idx);
    float4 b = *(const float4*)(s + idx + 4);
    *(uint4*)(d + idx) = make_uint4(
        f16x2_of(a.x, a.y), f16x2_of(a.z, a.w),
        f16x2_of(b.x, b.y), f16x2_of(b.z, b.w));
}

// ---------------------------------------------------------------------------
// fp16 GEMM (fp32 accumulate), 2-stage cp.async pipeline. (unchanged, R10)
// ---------------------------------------------------------------------------
#define GHS 72
#define ABUF (128 * GHS)
#define BBUF (64 * GHS)
#define GEMM_SMEM ((2 * ABUF + 2 * BBUF) * 2)

__device__ __forceinline__ void gemm_body(
    const __half* __restrict__ A, const __half* __restrict__ Bw,
    float* __restrict__ C, __half* __restrict__ Ch,
    int bm, int bn, int mode,
    const float* __restrict__ lng, const float* __restrict__ lnb, float lscale)
{
    extern __shared__ __half gsmh[];   // [A0][A1][B0][B1]
    float* red = (float*)gsmh;
    const uint32_t smem_u = (uint32_t)__cvta_generic_to_shared(gsmh);

    const int tid = threadIdx.x;
    const int lane = tid & 31, w = tid >> 5;
    const int q4 = lane & 3, r4 = lane >> 2;
    const int wm = (w & 3) * 32;
    const int wn = (w >> 2);
    const int wncol = wn * 32;

    const int arow[4] = { (tid + 0) >> 3, (tid + 256) >> 3, (tid + 512) >> 3, (tid + 768) >> 3 };
    const int brow[2] = { (tid + 0) >> 3, (tid + 256) >> 3 };
    const int hg = (tid & 7) * 8;

    const int lm_mat = lane >> 3, lm_r = lane & 7;
    const uint32_t alm_off =
        (uint32_t)(((wm + (lm_mat & 1) * 8 + lm_r) * GHS) + (lm_mat >> 1) * 8) * 2;
    const uint32_t blm_off = (uint32_t)(2 * ABUF) * 2 +
        (uint32_t)(((wncol + (lm_mat >> 1) * 8 + lm_r) * GHS) + (lm_mat & 1) * 8) * 2;

#pragma unroll
    for (int i = 0; i < 4; i++)
        cpa16(smem_u + (uint32_t)(arow[i] * GHS + hg) * 2,
              A + (size_t)(bm + arow[i]) * DIMSZ + hg);
#pragma unroll
    for (int i = 0; i < 2; i++)
        cpa16(smem_u + (uint32_t)(2 * ABUF + brow[i] * GHS + hg) * 2,
              Bw + (size_t)(bn + brow[i]) * DIMSZ + hg);
    cpa_commit();

    float acc[2][4][4];
#pragma unroll
    for (int mt = 0; mt < 2; mt++)
#pragma unroll
        for (int nt = 0; nt < 4; nt++)
#pragma unroll
            for (int c = 0; c < 4; c++) acc[mt][nt][c] = 0.f;

    for (int t = 0; t < 8; t++) {
        int st = t & 1;
        if (t < 7) {
            int kt = (t + 1) * 64;
            int ns = st ^ 1;
#pragma unroll
            for (int i = 0; i < 4; i++)
                cpa16(smem_u + (uint32_t)(ns * ABUF + arow[i] * GHS + hg) * 2,
                      A + (size_t)(bm + arow[i]) * DIMSZ + kt + hg);
#pragma unroll
            for (int i = 0; i < 2; i++)
                cpa16(smem_u + (uint32_t)(2 * ABUF + ns * BBUF + brow[i] * GHS + hg) * 2,
                      Bw + (size_t)(bn + brow[i]) * DIMSZ + kt + hg);
            cpa_commit();
            cpa_wait1();
        } else {
            cpa_wait0();
        }
        __syncthreads();

        const uint32_t abase = alm_off + (uint32_t)(st * ABUF) * 2 + smem_u;
        const uint32_t bbase = blm_off + (uint32_t)(st * BBUF) * 2 + smem_u;
#pragma unroll
        for (int kk = 0; kk < 4; kk++) {
            unsigned af[2][4];
#pragma unroll
            for (int mt = 0; mt < 2; mt++)
                ldsm4(af[mt][0], af[mt][1], af[mt][2], af[mt][3],
                      abase + (uint32_t)(mt * 16 * GHS + kk * 16) * 2);
#pragma unroll
            for (int nt2 = 0; nt2 < 2; nt2++) {
                unsigned b0, b1, b2, b3;
                ldsm4(b0, b1, b2, b3,
                      bbase + (uint32_t)(nt2 * 16 * GHS + kk * 16) * 2);
#pragma unroll
                for (int mt = 0; mt < 2; mt++) {
                    mma_f16(acc[mt][2 * nt2][0], acc[mt][2 * nt2][1],
                            acc[mt][2 * nt2][2], acc[mt][2 * nt2][3],
                            af[mt][0], af[mt][1], af[mt][2], af[mt][3], b0, b1);
                    mma_f16(acc[mt][2 * nt2 + 1][0], acc[mt][2 * nt2 + 1][1],
                            acc[mt][2 * nt2 + 1][2], acc[mt][2 * nt2 + 1][3],
                            af[mt][0], af[mt][1], af[mt][2], af[mt][3], b2, b3);
                }
            }
        }
        __syncthreads();
    }

    if (mode == 1 || mode == 3) {
#pragma unroll
        for (int mt = 0; mt < 2; mt++) {
#pragma unroll
            for (int half = 0; half < 2; half++) {
                float s = 0.f, ss = 0.f;
#pragma unroll
                for (int nt = 0; nt < 4; nt++) {
                    float v0 = acc[mt][nt][2 * half];
                    float v1 = acc[mt][nt][2 * half + 1];
                    s += v0 + v1;
                    ss += v0 * v0 + v1 * v1;
                }
                s += __shfl_xor_sync(0xffffffffu, s, 1);
                s += __shfl_xor_sync(0xffffffffu, s, 2);
                ss += __shfl_xor_sync(0xffffffffu, ss, 1);
                ss += __shfl_xor_sync(0xffffffffu, ss, 2);
                if (q4 == 0) {
                    int row = wm + mt * 16 + half * 8 + r4;
                    red[(wn * 128 + row) * 2 + 0] = s;
                    red[(wn * 128 + row) * 2 + 1] = ss;
                }
            }
        }
        __syncthreads();
#pragma unroll
        for (int mt = 0; mt < 2; mt++) {
#pragma unroll
            for (int half = 0; half < 2; half++) {
                int row = wm + mt * 16 + half * 8 + r4;
                float S  = red[row * 2 + 0] + red[(128 + row) * 2 + 0];
                float SS = red[row * 2 + 1] + red[(128 + row) * 2 + 1];
                float m = S * (1.f / 64.f);
                float var = SS * (1.f / 64.f) - m * m;
                float rr = rsqrtf(var + EPSLN);
#pragma unroll
                for (int nt = 0; nt < 4; nt++) {
                    int ci = wncol + nt * 8 + 2 * q4;
                    float o0 = ((acc[mt][nt][2 * half]     - m) * rr * lng[ci]     + lnb[ci])     * lscale;
                    float o1 = ((acc[mt][nt][2 * half + 1] - m) * rr * lng[ci + 1] + lnb[ci + 1]) * lscale;
                    if (mode == 1) {
                        float* cp = C + (size_t)(bm + row) * DIMSZ + bn + ci;
                        *(float2*)cp = make_float2(tf32f(o0), tf32f(o1));
                    } else {
                        __half* cp = Ch + (size_t)(bm + row) * DIMSZ + bn + ci;
                        *(__half2*)cp = __floats2half2_rn(o0, o1);
                    }
                }
            }
        }
    } else if (mode == 2) {
#pragma unroll
        for (int mt = 0; mt < 2; mt++) {
            int r0 = bm + wm + mt * 16 + r4;
#pragma unroll
            for (int nt = 0; nt < 4; nt++) {
                __half* cp = Ch + (size_t)r0 * DIMSZ + bn + wncol + nt * 8 + 2 * q4;
                *(__half2*)cp = __floats2half2_rn(acc[mt][nt][0], acc[mt][nt][1]);
                *(__half2*)(cp + (size_t)8 * DIMSZ) =
                    __floats2half2_rn(acc[mt][nt][2], acc[mt][nt][3]);
            }
        }
    } else {
#pragma unroll
        for (int mt = 0; mt < 2; mt++) {
            int r0 = bm + wm + mt * 16 + r4;
#pragma unroll
            for (int nt = 0; nt < 4; nt++) {
                float* cp = C + (size_t)r0 * DIMSZ + bn + wncol + nt * 8 + 2 * q4;
                *(float2*)cp = make_float2(acc[mt][nt][0], acc[mt][nt][1]);
                *(float2*)(cp + (size_t)8 * DIMSZ) =
                    make_float2(acc[mt][nt][2], acc[mt][nt][3]);
            }
        }
    }
}

__global__ __launch_bounds__(256, 2) void gemm_qkv(
    const __half* __restrict__ xh, const __half* __restrict__ wh,
    float* __restrict__ Qp, __half* __restrict__ Kp, __half* __restrict__ Vp,
    const float* __restrict__ qg, const float* __restrict__ qb,
    const float* __restrict__ kg, const float* __restrict__ kb)
{
    const int z = blockIdx.z;
    const __half* A  = xh + (size_t)z * BSROWS * DIMSZ;
    const __half* Bw = wh + (size_t)z * DIMSZ * DIMSZ;
    __half* Ch      = (z == 1) ? Kp : Vp;
    const float* g  = (z == 0) ? qg : kg;
    const float* bb = (z == 0) ? qb : kb;
    float sc        = (z == 0) ? 0.125f : 1.0f;
    int mode        = (z == 0) ? 1 : (z == 1) ? 3 : 2;
    gemm_body(A, Bw, Qp, Ch, blockIdx.y * 128, blockIdx.x * 64, mode, g, bb, sc);
}

__global__ __launch_bounds__(256, 2) void gemm_proj(
    const __half* __restrict__ A, const __half* __restrict__ Bw, float* __restrict__ C)
{
    gemm_body(A, Bw, C, nullptr, blockIdx.y * 128, blockIdx.x * 64, 0, nullptr, nullptr, 1.f);
}

// ---------------------------------------------------------------------------
// Full-row layernorm over D=512: fp32 in, fp16 out. One warp per row.
// ---------------------------------------------------------------------------
__global__ __launch_bounds__(256) void ln_full(
    const float* __restrict__ X, __half* __restrict__ Xh,
    const float* __restrict__ g, const float* __restrict__ bb)
{
    int row = blockIdx.x * 8 + (threadIdx.x >> 5);
    int lane = threadIdx.x & 31;
    const float* p = X + (size_t)row * DIMSZ;
    float4 x[4];
    float s = 0.f;
#pragma unroll
    for (int q = 0; q < 4; q++) {
        x[q] = *(const float4*)(p + lane * 4 + q * 128);
        s += x[q].x + x[q].y + x[q].z + x[q].w;
    }
#pragma unroll
    for (int off = 16; off; off >>= 1) s += __shfl_xor_sync(0xffffffffu, s, off);
    float m = s * (1.f / 512.f);
    float v = 0.f;
#pragma unroll
    for (int q = 0; q < 4; q++) {
        x[q].x -= m; x[q].y -= m; x[q].z -= m; x[q].w -= m;
        v += x[q].x * x[q].x + x[q].y * x[q].y + x[q].z * x[q].z + x[q].w * x[q].w;
    }
#pragma unroll
    for (int off = 16; off; off >>= 1) v += __shfl_xor_sync(0xffffffffu, v, off);
    float r = rsqrtf(v * (1.f / 512.f) + EPSLN);
#pragma unroll
    for (int q = 0; q < 4; q++) {
        int c = lane * 4 + q * 128;
        float4 gg = *(const float4*)(g + c);
        float4 bv = *(const float4*)(bb + c);
        uint2 st = make_uint2(
            f16x2_of(x[q].x * r * gg.x + bv.x, x[q].y * r * gg.y + bv.y),
            f16x2_of(x[q].z * r * gg.z + bv.z, x[q].w * r * gg.w + bv.w));
        *(uint2*)(Xh + (size_t)row * DIMSZ + c) = st;
    }
}

// ---------------------------------------------------------------------------
// Fused flash attention, fp16 operands, fixed-max softmax, cp.async
// double-buffered K/V in 128-key stages.
// 512 threads = 16 warps; warps 0-7 -> batch 2*bp, warps 8-15 -> batch 2*bp+1.
// Both batch-halves share the same smem K/V -> L2 K/V traffic halves.
// __launch_bounds__(512, 1): full register budget, NO spills (R12 bug fix).
// Grid = 128 blocks (batch-pair x head) = one clean wave on 148 SMs.
// ---------------------------------------------------------------------------
#define HSTR 72
#define KVS (128 * HSTR)                 // halves per stage per tensor
#define ATTN_SMEM (4 * KVS * 2)          // K0 K1 V0 V1, bytes
#define NSTG (NB / 128)                  // 32 stages
#define PEXPC 7.2134752f                 // 5.0 * log2(e)

__global__ __launch_bounds__(512, 1) void attn_mma(
    const float* __restrict__ Q, const __half* __restrict__ Kb,
    const __half* __restrict__ Vb, float* __restrict__ Xo)
{
    extern __shared__ __half asm_h[];    // [K st0][K st1][V st0][V st1]
    const uint32_t sm_u = (uint32_t)__cvta_generic_to_shared(asm_h);

    const int bph = blockIdx.x;
    const int bp = bph >> 3, h = bph & 7;
    const int tid = threadIdx.x;
    const int w = tid >> 5, lane = tid & 31;
    const int wq = w & 7, wb = w >> 3;          // query-warp slot, batch half
    const int b = bp * 2 + wb;
    const int q4 = lane & 3, r4 = lane >> 2;

    const __half* kbase = Kb + h * HDIM;
    const __half* vbase = Vb + h * HDIM;

    // fill coords: 2 chunks of 16B per tensor per thread per stage (512 thr)
    int cj[2];
    const int chg = (tid & 7) * 8;
#pragma unroll
    for (int i = 0; i < 2; i++) cj[i] = (tid + i * 512) >> 3;   // key 0..127

    const int lm_mat = lane >> 3, lm_r = lane & 7;
    const uint32_t klm_off =
        (uint32_t)(((lm_mat >> 1) * 8 + lm_r) * HSTR + (lm_mat & 1) * 8) * 2;
    const uint32_t vlm_off =
        (uint32_t)(((lm_mat & 1) * 8 + lm_r) * HSTR + (lm_mat >> 1) * 8) * 2;

    // issue stage 0
#pragma unroll
    for (int i = 0; i < 2; i++) {
        cpa16(sm_u + (uint32_t)(cj[i] * HSTR + chg) * 2,
              kbase + (size_t)cj[i] * DIMSZ + chg);
        cpa16(sm_u + (uint32_t)(2 * KVS + cj[i] * HSTR + chg) * 2,
              vbase + (size_t)cj[i] * DIMSZ + chg);
    }
    cpa_commit();

    // Q fragments: fp16, 4 k16-tiles x 4 regs
    unsigned qa[4][4];
    {
        const float* q0 = Q + (size_t)(b * SQ + wq * 16 + r4) * DIMSZ + h * HDIM;
        const float* q1 = q0 + 8 * DIMSZ;
#pragma unroll
        for (int kk = 0; kk < 4; kk++) {
            int col = kk * 16 + 2 * q4;
            qa[kk][0] = f16x2_of(q0[col],     q0[col + 1]);
            qa[kk][1] = f16x2_of(q1[col],     q1[col + 1]);
            qa[kk][2] = f16x2_of(q0[col + 8], q0[col + 9]);
            qa[kk][3] = f16x2_of(q1[col + 8], q1[col + 9]);
        }
    }

    float lA = 0.f, lB = 0.f;
    float o[8][4];
#pragma unroll
    for (int dt = 0; dt < 8; dt++)
        o[dt][0] = o[dt][1] = o[dt][2] = o[dt][3] = 0.f;

    for (int t = 0; t < NSTG; t++) {
        int st = t & 1;
        if (t + 1 < NSTG) {
            int n1 = (t + 1) * 128;
            int ns = st ^ 1;
#pragma unroll
            for (int i = 0; i < 2; i++) {
                cpa16(sm_u + (uint32_t)(ns * KVS + cj[i] * HSTR + chg) * 2,
                      kbase + (size_t)(n1 + cj[i]) * DIMSZ + chg);
                cpa16(sm_u + (uint32_t)(2 * KVS + ns * KVS + cj[i] * HSTR + chg) * 2,
                      vbase + (size_t)(n1 + cj[i]) * DIMSZ + chg);
            }
            cpa_commit();
            cpa_wait1();
        } else {
            cpa_wait0();
        }
        __syncthreads();

#pragma unroll
        for (int sub = 0; sub < 2; sub++) {
            const uint32_t kbb = sm_u + (uint32_t)(st * KVS + sub * 64 * HSTR) * 2 + klm_off;
            const uint32_t vbb = sm_u + (uint32_t)(2 * KVS + st * KVS + sub * 64 * HSTR) * 2 + vlm_off;

            // ---- scores: S = Q K^T ----
            float s[8][4];
#pragma unroll
            for (int nt = 0; nt < 8; nt++)
                s[nt][0] = s[nt][1] = s[nt][2] = s[nt][3] = 0.f;
#pragma unroll
            for (int kk = 0; kk < 4; kk++) {
#pragma unroll
                for (int nt2 = 0; nt2 < 4; nt2++) {
                    unsigned b0, b1, b2, b3;
                    ldsm4(b0, b1, b2, b3,
                          kbb + (uint32_t)(nt2 * 16 * HSTR + kk * 16) * 2);
                    mma_f16(s[2 * nt2][0], s[2 * nt2][1], s[2 * nt2][2], s[2 * nt2][3],
                            qa[kk][0], qa[kk][1], qa[kk][2], qa[kk][3], b0, b1);
                    mma_f16(s[2 * nt2 + 1][0], s[2 * nt2 + 1][1], s[2 * nt2 + 1][2], s[2 * nt2 + 1][3],
                            qa[kk][0], qa[kk][1], qa[kk][2], qa[kk][3], b2, b3);
                }
            }

            // ---- fixed-max softmax; pack P into fp16 A-fragments ----
            float suA = 0.f, suB = 0.f;
            unsigned ph[4][4];
#pragma unroll
            for (int nt = 0; nt < 8; nt++) {
                float p0 = exp2f(fmaf(s[nt][0], 1.44269504f, -PEXPC));
                float p1 = exp2f(fmaf(s[nt][1], 1.44269504f, -PEXPC));
                float p2 = exp2f(fmaf(s[nt][2], 1.44269504f, -PEXPC));
                float p3 = exp2f(fmaf(s[nt][3], 1.44269504f, -PEXPC));
                suA += p0 + p1; suB += p2 + p3;
                int tt = nt >> 1;
                if ((nt & 1) == 0) {
                    ph[tt][0] = f16x2_of(p0, p1);
                    ph[tt][1] = f16x2_of(p2, p3);
                } else {
                    ph[tt][2] = f16x2_of(p0, p1);
                    ph[tt][3] = f16x2_of(p2, p3);
                }
            }
            lA += suA;
            lB += suB;

            // ---- O += P @ V ----
#pragma unroll
            for (int kk = 0; kk < 4; kk++) {
#pragma unroll
                for (int dt2 = 0; dt2 < 4; dt2++) {
                    unsigned v0, v1, v2, v3;
                    ldsm4t(v0, v1, v2, v3,
                           vbb + (uint32_t)(kk * 16 * HSTR + dt2 * 16) * 2);
                    mma_f16(o[2 * dt2][0], o[2 * dt2][1], o[2 * dt2][2], o[2 * dt2][3],
                            ph[kk][0], ph[kk][1], ph[kk][2], ph[kk][3], v0, v1);
                    mma_f16(o[2 * dt2 + 1][0], o[2 * dt2 + 1][1], o[2 * dt2 + 1][2], o[2 * dt2 + 1][3],
                            ph[kk][0], ph[kk][1], ph[kk][2], ph[kk][3], v2, v3);
                }
            }
        }
        __syncthreads();   // all warps done reading stage before refill
    }

    lA += __shfl_xor_sync(0xffffffffu, lA, 1);
    lA += __shfl_xor_sync(0xffffffffu, lA, 2);
    lB += __shfl_xor_sync(0xffffffffu, lB, 1);
    lB += __shfl_xor_sync(0xffffffffu, lB, 2);
    float ivA = 1.f / lA, ivB = 1.f / lB;
    int rowA = b * SQ + wq * 16 + r4;
    float* xoA = Xo + (size_t)rowA * DIMSZ + h * HDIM + 2 * q4;
    float* xoB = xoA + 8 * DIMSZ;
#pragma unroll
    for (int dt = 0; dt < 8; dt++) {
        *(float2*)(xoA + dt * 8) = make_float2(o[dt][0] * ivA, o[dt][1] * ivA);
        *(float2*)(xoB + dt * 8) = make_float2(o[dt][2] * ivB, o[dt][3] * ivB);
    }
}

// ---------------------------------------------------------------------------
extern "C" void kernel_launch(void* const* d_in, const int* in_sizes, int n_in,
                              void* d_out, int out_size)
{
    const float* x_q   = (const float*)d_in[0];
    const float* x_k   = (const float*)d_in[1];
    const float* x_v   = (const float*)d_in[2];
    const float* Wq    = (const float*)d_in[3];
    const float* Wk    = (const float*)d_in[4];
    const float* Wv    = (const float*)d_in[5];
    const float* Wproj = (const float*)d_in[6];
    const float* qn_g  = (const float*)d_in[7];
    const float* qn_b  = (const float*)d_in[8];
    const float* kn_g  = (const float*)d_in[9];
    const float* kn_b  = (const float*)d_in[10];
    const float* n_g   = (const float*)d_in[11];
    const float* n_b   = (const float*)d_in[12];
    float* out = (float*)d_out;

    float *Qp, *Xp;
    __half *Kp, *Vp, *xh, *wh, *Xh;
    cudaGetSymbolAddress((void**)&Qp, g_Q);
    cudaGetSymbolAddress((void**)&Kp, g_K);
    cudaGetSymbolAddress((void**)&Vp, g_V);
    cudaGetSymbolAddress((void**)&Xp, g_X);
    cudaGetSymbolAddress((void**)&xh, g_xh);
    cudaGetSymbolAddress((void**)&wh, g_wh);
    cudaGetSymbolAddress((void**)&Xh, g_Xh);

    static bool attr_set = false;
    if (!attr_set) {
        cudaFuncSetAttribute(gemm_qkv,
                             cudaFuncAttributeMaxDynamicSharedMemorySize, GEMM_SMEM);
        cudaFuncSetAttribute(gemm_proj,
                             cudaFuncAttributeMaxDynamicSharedMemorySize, GEMM_SMEM);
        cudaFuncSetAttribute(attn_mma,
                             cudaFuncAttributeMaxDynamicSharedMemorySize, ATTN_SMEM);
        attr_set = true;
    }

    // fp32 -> fp16 inputs (x_q/x_k/x_v + 4 weights)
    dim3 cvt_grid(BSROWS * DIMSZ / (256 * 8), 7);
    cvt_f2h<<<cvt_grid, 256>>>(x_q, x_k, x_v, Wq, Wk, Wv, Wproj, xh, wh);

    // fused Q/K/V projections + per-head LN / fp16 epilogues (cp.async pipelined)
    dim3 qkv_grid(DIMSZ / 64, BSROWS / 128, 3);
    gemm_qkv<<<qkv_grid, 256, GEMM_SMEM>>>(xh, wh, Qp, Kp, Vp,
                                           qn_g, qn_b, kn_g, kn_b);

    // fused attention (fp16, fixed-max softmax, 2 batches per block)
    attn_mma<<<(BSZ / 2) * NHEAD, 512, ATTN_SMEM>>>(Qp, Kp, Vp, Xp);

    // output layernorm (fp16 out) + projection
    ln_full<<<BSROWS / 8, 256>>>(Xp, Xh, n_g, n_b);
    dim3 proj_grid(DIMSZ / 64, BSROWS / 128);
    gemm_proj<<<proj_grid, 256, GEMM_SMEM>>>(Xh, wh + 3 * DIMSZ * DIMSZ, out);
}

// round 14
// speedup vs baseline: 2.1167x; 1.5160x over previous
#include <cuda_runtime.h>
#include <cuda_fp16.h>
#include <cstdint>

#define DIMSZ 512
#define NHEAD 8
#define HDIM  64
#define NB    4096
#define BSZ   32
#define SQ    128
#define BSROWS 4096
#define EPSLN 1e-5f

// scratch (allocation-free rule: __device__ globals)
__device__ __half g_xh[3 * BSROWS * DIMSZ];   // x_q, x_k, x_v in fp16
__device__ __half g_wh[4 * DIMSZ * DIMSZ];    // Wq, Wk, Wv, Wproj in fp16
__device__ __half g_Qh[BSROWS * DIMSZ];
__device__ __half g_K[NB * DIMSZ];
__device__ __half g_V[NB * DIMSZ];
__device__ float  g_X[BSROWS * DIMSZ];
__device__ __half g_Xh[BSROWS * DIMSZ];

// ---------------------------------------------------------------------------
// helpers
// ---------------------------------------------------------------------------
__device__ __forceinline__ void mma_f16(
    float& c0, float& c1, float& c2, float& c3,
    unsigned a0, unsigned a1, unsigned a2, unsigned a3,
    unsigned b0, unsigned b1)
{
    asm volatile(
        "mma.sync.aligned.m16n8k16.row.col.f32.f16.f16.f32 "
        "{%0,%1,%2,%3}, {%4,%5,%6,%7}, {%8,%9}, {%0,%1,%2,%3};"
        : "+f"(c0), "+f"(c1), "+f"(c2), "+f"(c3)
        : "r"(a0), "r"(a1), "r"(a2), "r"(a3), "r"(b0), "r"(b1));
}
__device__ __forceinline__ unsigned f16x2_of(float lo, float hi) {
    unsigned d;
    asm("cvt.rn.f16x2.f32 %0, %1, %2;" : "=r"(d) : "f"(hi), "f"(lo));
    return d;
}
__device__ __forceinline__ void ldsm4(
    unsigned& r0, unsigned& r1, unsigned& r2, unsigned& r3, uint32_t addr)
{
    asm volatile(
        "ldmatrix.sync.aligned.m8n8.x4.shared.b16 {%0,%1,%2,%3}, [%4];"
        : "=r"(r0), "=r"(r1), "=r"(r2), "=r"(r3) : "r"(addr));
}
__device__ __forceinline__ void ldsm4t(
    unsigned& r0, unsigned& r1, unsigned& r2, unsigned& r3, uint32_t addr)
{
    asm volatile(
        "ldmatrix.sync.aligned.m8n8.x4.trans.shared.b16 {%0,%1,%2,%3}, [%4];"
        : "=r"(r0), "=r"(r1), "=r"(r2), "=r"(r3) : "r"(addr));
}
__device__ __forceinline__ void cpa16(uint32_t s, const void* g) {
    asm volatile("cp.async.cg.shared.global [%0], [%1], 16;" :: "r"(s), "l"(g));
}
__device__ __forceinline__ void cpa_commit() { asm volatile("cp.async.commit_group;"); }
__device__ __forceinline__ void cpa_wait1()  { asm volatile("cp.async.wait_group 1;"); }
__device__ __forceinline__ void cpa_wait0()  { asm volatile("cp.async.wait_group 0;"); }

// ---------------------------------------------------------------------------
// fp32 -> fp16 conversion pass for x_q/x_k/x_v (z=0..2) and W's (z=3..6)
// ---------------------------------------------------------------------------
__global__ __launch_bounds__(256) void cvt_f2h(
    const float* __restrict__ x_q, const float* __restrict__ x_k,
    const float* __restrict__ x_v,
    const float* __restrict__ Wq, const float* __restrict__ Wk,
    const float* __restrict__ Wv, const float* __restrict__ Wp,
    __half* __restrict__ xh, __half* __restrict__ wh)
{
    int z = blockIdx.y;
    const float* s;
    __half* d;
    int n;
    if (z < 3) {
        s = (z == 0) ? x_q : (z == 1) ? x_k : x_v;
        d = xh + (size_t)z * BSROWS * DIMSZ;
        n = BSROWS * DIMSZ;
    } else {
        int zz = z - 3;
        s = (zz == 0) ? Wq : (zz == 1) ? Wk : (zz == 2) ? Wv : Wp;
        d = wh + (size_t)zz * DIMSZ * DIMSZ;
        n = DIMSZ * DIMSZ;
    }
    int idx = (blockIdx.x * 256 + threadIdx.x) * 8;
    if (idx >= n) return;
    float4 a = *(const float4*)(s + idx);
    float4 b = *(const float4*)(s + idx + 4);
    *(uint4*)(d + idx) = make_uint4(
        f16x2_of(a.x, a.y), f16x2_of(a.z, a.w),
        f16x2_of(b.x, b.y), f16x2_of(b.z, b.w));
}

// ---------------------------------------------------------------------------
// fp16 GEMM (fp32 accumulate), 3-stage cp.async pipeline, ONE sync per k-tile.
// Issue of stage t+2 happens AFTER the sync of iter t -> buffer (t+2)%3 ==
// (t-1)%3 is provably idle. C[m][n] = sum_k A[m][k]*Bw[n][k].
// BM=128, BN=64, BK=64, 8 warps (4m x 2n).
// Epilogue modes: 0 plain fp32, 1 per-head LN -> fp16 (Q),
//                 2 fp16 out (V), 3 per-head LN -> fp16 (K).
// ---------------------------------------------------------------------------
#define GHS 72
#define ABUF (128 * GHS)
#define BBUF (64 * GHS)
#define NKT  (DIMSZ / 64)                   // 8 k-tiles
#define GEMM_SMEM ((3 * ABUF + 3 * BBUF) * 2)

__device__ __forceinline__ void gemm_fill(
    uint32_t smem_u, int stage,
    const __half* __restrict__ A, const __half* __restrict__ Bw,
    int bm, int bn, int kt,
    const int* arow, const int* brow, int hg)
{
#pragma unroll
    for (int i = 0; i < 4; i++)
        cpa16(smem_u + (uint32_t)(stage * ABUF + arow[i] * GHS + hg) * 2,
              A + (size_t)(bm + arow[i]) * DIMSZ + kt + hg);
#pragma unroll
    for (int i = 0; i < 2; i++)
        cpa16(smem_u + (uint32_t)(3 * ABUF + stage * BBUF + brow[i] * GHS + hg) * 2,
              Bw + (size_t)(bn + brow[i]) * DIMSZ + kt + hg);
    cpa_commit();
}

__device__ __forceinline__ void gemm_body(
    const __half* __restrict__ A, const __half* __restrict__ Bw,
    float* __restrict__ C, __half* __restrict__ Ch,
    int bm, int bn, int mode,
    const float* __restrict__ lng, const float* __restrict__ lnb, float lscale)
{
    extern __shared__ __half gsmh[];   // [A0][A1][A2][B0][B1][B2]
    float* red = (float*)gsmh;         // LN reduce buffer aliases A0 in epilogue
    const uint32_t smem_u = (uint32_t)__cvta_generic_to_shared(gsmh);

    const int tid = threadIdx.x;
    const int lane = tid & 31, w = tid >> 5;
    const int q4 = lane & 3, r4 = lane >> 2;
    const int wm = (w & 3) * 32;
    const int wn = (w >> 2);
    const int wncol = wn * 32;

    const int arow[4] = { (tid + 0) >> 3, (tid + 256) >> 3, (tid + 512) >> 3, (tid + 768) >> 3 };
    const int brow[2] = { (tid + 0) >> 3, (tid + 256) >> 3 };
    const int hg = (tid & 7) * 8;

    const int lm_mat = lane >> 3, lm_r = lane & 7;
    const uint32_t alm_off =
        (uint32_t)(((wm + (lm_mat & 1) * 8 + lm_r) * GHS) + (lm_mat >> 1) * 8) * 2;
    const uint32_t blm_off = (uint32_t)(3 * ABUF) * 2 +
        (uint32_t)(((wncol + (lm_mat >> 1) * 8 + lm_r) * GHS) + (lm_mat & 1) * 8) * 2;

    // prologue: stages 0 and 1
    gemm_fill(smem_u, 0, A, Bw, bm, bn, 0, arow, brow, hg);
    gemm_fill(smem_u, 1, A, Bw, bm, bn, 64, arow, brow, hg);

    float acc[2][4][4];
#pragma unroll
    for (int mt = 0; mt < 2; mt++)
#pragma unroll
        for (int nt = 0; nt < 4; nt++)
#pragma unroll
            for (int c = 0; c < 4; c++) acc[mt][nt][c] = 0.f;

    for (int t = 0; t < NKT; t++) {
        int st = t % 3;
        if (t + 1 < NKT) cpa_wait1(); else cpa_wait0();
        __syncthreads();
        if (t + 2 < NKT)
            gemm_fill(smem_u, (t + 2) % 3, A, Bw, bm, bn, (t + 2) * 64, arow, brow, hg);

        const uint32_t abase = alm_off + (uint32_t)(st * ABUF) * 2 + smem_u;
        const uint32_t bbase = blm_off + (uint32_t)(st * BBUF) * 2 + smem_u;
#pragma unroll
        for (int kk = 0; kk < 4; kk++) {
            unsigned af[2][4];
#pragma unroll
            for (int mt = 0; mt < 2; mt++)
                ldsm4(af[mt][0], af[mt][1], af[mt][2], af[mt][3],
                      abase + (uint32_t)(mt * 16 * GHS + kk * 16) * 2);
#pragma unroll
            for (int nt2 = 0; nt2 < 2; nt2++) {
                unsigned b0, b1, b2, b3;
                ldsm4(b0, b1, b2, b3,
                      bbase + (uint32_t)(nt2 * 16 * GHS + kk * 16) * 2);
#pragma unroll
                for (int mt = 0; mt < 2; mt++) {
                    mma_f16(acc[mt][2 * nt2][0], acc[mt][2 * nt2][1],
                            acc[mt][2 * nt2][2], acc[mt][2 * nt2][3],
                            af[mt][0], af[mt][1], af[mt][2], af[mt][3], b0, b1);
                    mma_f16(acc[mt][2 * nt2 + 1][0], acc[mt][2 * nt2 + 1][1],
                            acc[mt][2 * nt2 + 1][2], acc[mt][2 * nt2 + 1][3],
                            af[mt][0], af[mt][1], af[mt][2], af[mt][3], b2, b3);
                }
            }
        }
    }

    if (mode == 1 || mode == 3) {
        // -------- fused per-head layernorm (fp16 out) --------
        __syncthreads();   // all warps done with smem tiles before red alias
#pragma unroll
        for (int mt = 0; mt < 2; mt++) {
#pragma unroll
            for (int half = 0; half < 2; half++) {
                float s = 0.f, ss = 0.f;
#pragma unroll
                for (int nt = 0; nt < 4; nt++) {
                    float v0 = acc[mt][nt][2 * half];
                    float v1 = acc[mt][nt][2 * half + 1];
                    s += v0 + v1;
                    ss += v0 * v0 + v1 * v1;
                }
                s += __shfl_xor_sync(0xffffffffu, s, 1);
                s += __shfl_xor_sync(0xffffffffu, s, 2);
                ss += __shfl_xor_sync(0xffffffffu, ss, 1);
                ss += __shfl_xor_sync(0xffffffffu, ss, 2);
                if (q4 == 0) {
                    int row = wm + mt * 16 + half * 8 + r4;
                    red[(wn * 128 + row) * 2 + 0] = s;
                    red[(wn * 128 + row) * 2 + 1] = ss;
                }
            }
        }
        __syncthreads();
#pragma unroll
        for (int mt = 0; mt < 2; mt++) {
#pragma unroll
            for (int half = 0; half < 2; half++) {
                int row = wm + mt * 16 + half * 8 + r4;
                float S  = red[row * 2 + 0] + red[(128 + row) * 2 + 0];
                float SS = red[row * 2 + 1] + red[(128 + row) * 2 + 1];
                float m = S * (1.f / 64.f);
                float var = SS * (1.f / 64.f) - m * m;
                float rr = rsqrtf(var + EPSLN);
#pragma unroll
                for (int nt = 0; nt < 4; nt++) {
                    int ci = wncol + nt * 8 + 2 * q4;
                    float o0 = ((acc[mt][nt][2 * half]     - m) * rr * lng[ci]     + lnb[ci])     * lscale;
                    float o1 = ((acc[mt][nt][2 * half + 1] - m) * rr * lng[ci + 1] + lnb[ci + 1]) * lscale;
                    __half* cp = Ch + (size_t)(bm + row) * DIMSZ + bn + ci;
                    *(__half2*)cp = __floats2half2_rn(o0, o1);
                }
            }
        }
    } else if (mode == 2) {
#pragma unroll
        for (int mt = 0; mt < 2; mt++) {
            int r0 = bm + wm + mt * 16 + r4;
#pragma unroll
            for (int nt = 0; nt < 4; nt++) {
                __half* cp = Ch + (size_t)r0 * DIMSZ + bn + wncol + nt * 8 + 2 * q4;
                *(__half2*)cp = __floats2half2_rn(acc[mt][nt][0], acc[mt][nt][1]);
                *(__half2*)(cp + (size_t)8 * DIMSZ) =
                    __floats2half2_rn(acc[mt][nt][2], acc[mt][nt][3]);
            }
        }
    } else {
#pragma unroll
        for (int mt = 0; mt < 2; mt++) {
            int r0 = bm + wm + mt * 16 + r4;
#pragma unroll
            for (int nt = 0; nt < 4; nt++) {
                float* cp = C + (size_t)r0 * DIMSZ + bn + wncol + nt * 8 + 2 * q4;
                *(float2*)cp = make_float2(acc[mt][nt][0], acc[mt][nt][1]);
                *(float2*)(cp + (size_t)8 * DIMSZ) =
                    make_float2(acc[mt][nt][2], acc[mt][nt][3]);
            }
        }
    }
}

__global__ __launch_bounds__(256, 2) void gemm_qkv(
    const __half* __restrict__ xh, const __half* __restrict__ wh,
    __half* __restrict__ Qh, __half* __restrict__ Kp, __half* __restrict__ Vp,
    const float* __restrict__ qg, const float* __restrict__ qb,
    const float* __restrict__ kg, const float* __restrict__ kb)
{
    const int z = blockIdx.z;
    const __half* A  = xh + (size_t)z * BSROWS * DIMSZ;
    const __half* Bw = wh + (size_t)z * DIMSZ * DIMSZ;
    __half* Ch      = (z == 0) ? Qh : (z == 1) ? Kp : Vp;
    const float* g  = (z == 0) ? qg : kg;
    const float* bb = (z == 0) ? qb : kb;
    float sc        = (z == 0) ? 0.125f : 1.0f;
    int mode        = (z == 0) ? 1 : (z == 1) ? 3 : 2;
    gemm_body(A, Bw, nullptr, Ch, blockIdx.y * 128, blockIdx.x * 64, mode, g, bb, sc);
}

__global__ __launch_bounds__(256, 2) void gemm_proj(
    const __half* __restrict__ A, const __half* __restrict__ Bw, float* __restrict__ C)
{
    gemm_body(A, Bw, C, nullptr, blockIdx.y * 128, blockIdx.x * 64, 0, nullptr, nullptr, 1.f);
}

// ---------------------------------------------------------------------------
// Full-row layernorm over D=512: fp32 in, fp16 out. One warp per row.
// ---------------------------------------------------------------------------
__global__ __launch_bounds__(256) void ln_full(
    const float* __restrict__ X, __half* __restrict__ Xh,
    const float* __restrict__ g, const float* __restrict__ bb)
{
    int row = blockIdx.x * 8 + (threadIdx.x >> 5);
    int lane = threadIdx.x & 31;
    const float* p = X + (size_t)row * DIMSZ;
    float4 x[4];
    float s = 0.f;
#pragma unroll
    for (int q = 0; q < 4; q++) {
        x[q] = *(const float4*)(p + lane * 4 + q * 128);
        s += x[q].x + x[q].y + x[q].z + x[q].w;
    }
#pragma unroll
    for (int off = 16; off; off >>= 1) s += __shfl_xor_sync(0xffffffffu, s, off);
    float m = s * (1.f / 512.f);
    float v = 0.f;
#pragma unroll
    for (int q = 0; q < 4; q++) {
        x[q].x -= m; x[q].y -= m; x[q].z -= m; x[q].w -= m;
        v += x[q].x * x[q].x + x[q].y * x[q].y + x[q].z * x[q].z + x[q].w * x[q].w;
    }
#pragma unroll
    for (int off = 16; off; off >>= 1) v += __shfl_xor_sync(0xffffffffu, v, off);
    float r = rsqrtf(v * (1.f / 512.f) + EPSLN);
#pragma unroll
    for (int q = 0; q < 4; q++) {
        int c = lane * 4 + q * 128;
        float4 gg = *(const float4*)(g + c);
        float4 bv = *(const float4*)(bb + c);
        uint2 st = make_uint2(
            f16x2_of(x[q].x * r * gg.x + bv.x, x[q].y * r * gg.y + bv.y),
            f16x2_of(x[q].z * r * gg.z + bv.z, x[q].w * r * gg.w + bv.w));
        *(uint2*)(Xh + (size_t)row * DIMSZ + c) = st;
    }
}

// ---------------------------------------------------------------------------
// Fused flash attention (R11 config, best known): fp16 operands, fixed-max
// softmax, cp.async double-buffered K/V in 128-key stages.
// One block per (b,h). 256 threads = 8 warps, 16 query rows per warp.
// Q arrives fp16 -> fragment load is 16 aligned 32-bit loads, zero cvt.
// ---------------------------------------------------------------------------
#define HSTR 72
#define KVS (128 * HSTR)                 // halves per stage per tensor
#define ATTN_SMEM (4 * KVS * 2)          // K0 K1 V0 V1, bytes
#define NSTG (NB / 128)                  // 32 stages
#define PEXPC 7.2134752f                 // 5.0 * log2(e)

__global__ __launch_bounds__(256, 2) void attn_mma(
    const __half* __restrict__ Qh, const __half* __restrict__ Kb,
    const __half* __restrict__ Vb, float* __restrict__ Xo)
{
    extern __shared__ __half asm_h[];    // [K st0][K st1][V st0][V st1]
    const uint32_t sm_u = (uint32_t)__cvta_generic_to_shared(asm_h);

    const int bh = blockIdx.x;
    const int b = bh >> 3, h = bh & 7;
    const int tid = threadIdx.x;
    const int w = tid >> 5, lane = tid & 31;
    const int q4 = lane & 3, r4 = lane >> 2;

    const __half* kbase = Kb + h * HDIM;
    const __half* vbase = Vb + h * HDIM;

    // fill coords: 4 chunks of 16B per tensor per thread per stage
    int cj[4];
    const int chg = (tid & 7) * 8;
#pragma unroll
    for (int i = 0; i < 4; i++) cj[i] = (tid + i * 256) >> 3;   // key 0..127

    const int lm_mat = lane >> 3, lm_r = lane & 7;
    const uint32_t klm_off =
        (uint32_t)(((lm_mat >> 1) * 8 + lm_r) * HSTR + (lm_mat & 1) * 8) * 2;
    const uint32_t vlm_off =
        (uint32_t)(((lm_mat & 1) * 8 + lm_r) * HSTR + (lm_mat >> 1) * 8) * 2;

    // issue stage 0
#pragma unroll
    for (int i = 0; i < 4; i++) {
        cpa16(sm_u + (uint32_t)(cj[i] * HSTR + chg) * 2,
              kbase + (size_t)cj[i] * DIMSZ + chg);
        cpa16(sm_u + (uint32_t)(2 * KVS + cj[i] * HSTR + chg) * 2,
              vbase + (size_t)cj[i] * DIMSZ + chg);
    }
    cpa_commit();

    // Q fragments: fp16 in gmem, adjacent pairs -> direct 32-bit loads
    unsigned qa[4][4];
    {
        const __half* q0 = Qh + (size_t)(b * SQ + w * 16 + r4) * DIMSZ + h * HDIM;
        const __half* q1 = q0 + 8 * DIMSZ;
#pragma unroll
        for (int kk = 0; kk < 4; kk++) {
            int col = kk * 16 + 2 * q4;
            qa[kk][0] = *(const unsigned*)(q0 + col);
            qa[kk][1] = *(const unsigned*)(q1 + col);
            qa[kk][2] = *(const unsigned*)(q0 + col + 8);
            qa[kk][3] = *(const unsigned*)(q1 + col + 8);
        }
    }

    float lA = 0.f, lB = 0.f;
    float o[8][4];
#pragma unroll
    for (int dt = 0; dt < 8; dt++)
        o[dt][0] = o[dt][1] = o[dt][2] = o[dt][3] = 0.f;

    for (int t = 0; t < NSTG; t++) {
        int st = t & 1;
        if (t + 1 < NSTG) {
            int n1 = (t + 1) * 128;
            int ns = st ^ 1;
#pragma unroll
            for (int i = 0; i < 4; i++) {
                cpa16(sm_u + (uint32_t)(ns * KVS + cj[i] * HSTR + chg) * 2,
                      kbase + (size_t)(n1 + cj[i]) * DIMSZ + chg);
                cpa16(sm_u + (uint32_t)(2 * KVS + ns * KVS + cj[i] * HSTR + chg) * 2,
                      vbase + (size_t)(n1 + cj[i]) * DIMSZ + chg);
            }
            cpa_commit();
            cpa_wait1();
        } else {
            cpa_wait0();
        }
        __syncthreads();

#pragma unroll
        for (int sub = 0; sub < 2; sub++) {
            const uint32_t kbb = sm_u + (uint32_t)(st * KVS + sub * 64 * HSTR) * 2 + klm_off;
            const uint32_t vbb = sm_u + (uint32_t)(2 * KVS + st * KVS + sub * 64 * HSTR) * 2 + vlm_off;

            // ---- scores: S = Q K^T ----
            float s[8][4];
#pragma unroll
            for (int nt = 0; nt < 8; nt++)
                s[nt][0] = s[nt][1] = s[nt][2] = s[nt][3] = 0.f;
#pragma unroll
            for (int kk = 0; kk < 4; kk++) {
#pragma unroll
                for (int nt2 = 0; nt2 < 4; nt2++) {
                    unsigned b0, b1, b2, b3;
                    ldsm4(b0, b1, b2, b3,
                          kbb + (uint32_t)(nt2 * 16 * HSTR + kk * 16) * 2);
                    mma_f16(s[2 * nt2][0], s[2 * nt2][1], s[2 * nt2][2], s[2 * nt2][3],
                            qa[kk][0], qa[kk][1], qa[kk][2], qa[kk][3], b0, b1);
                    mma_f16(s[2 * nt2 + 1][0], s[2 * nt2 + 1][1], s[2 * nt2 + 1][2], s[2 * nt2 + 1][3],
                            qa[kk][0], qa[kk][1], qa[kk][2], qa[kk][3], b2, b3);
                }
            }

            // ---- fixed-max softmax; pack P into fp16 A-fragments ----
            float suA = 0.f, suB = 0.f;
            unsigned ph[4][4];
#pragma unroll
            for (int nt = 0; nt < 8; nt++) {
                float p0 = exp2f(fmaf(s[nt][0], 1.44269504f, -PEXPC));
                float p1 = exp2f(fmaf(s[nt][1], 1.44269504f, -PEXPC));
                float p2 = exp2f(fmaf(s[nt][2], 1.44269504f, -PEXPC));
                float p3 = exp2f(fmaf(s[nt][3], 1.44269504f, -PEXPC));
                suA += p0 + p1; suB += p2 + p3;
                int tt = nt >> 1;
                if ((nt & 1) == 0) {
                    ph[tt][0] = f16x2_of(p0, p1);
                    ph[tt][1] = f16x2_of(p2, p3);
                } else {
                    ph[tt][2] = f16x2_of(p0, p1);
                    ph[tt][3] = f16x2_of(p2, p3);
                }
            }
            lA += suA;
            lB += suB;

            // ---- O += P @ V ----
#pragma unroll
            for (int kk = 0; kk < 4; kk++) {
#pragma unroll
                for (int dt2 = 0; dt2 < 4; dt2++) {
                    unsigned v0, v1, v2, v3;
                    ldsm4t(v0, v1, v2, v3,
                           vbb + (uint32_t)(kk * 16 * HSTR + dt2 * 16) * 2);
                    mma_f16(o[2 * dt2][0], o[2 * dt2][1], o[2 * dt2][2], o[2 * dt2][3],
                            ph[kk][0], ph[kk][1], ph[kk][2], ph[kk][3], v0, v1);
                    mma_f16(o[2 * dt2 + 1][0], o[2 * dt2 + 1][1], o[2 * dt2 + 1][2], o[2 * dt2 + 1][3],
                            ph[kk][0], ph[kk][1], ph[kk][2], ph[kk][3], v2, v3);
                }
            }
        }
        __syncthreads();   // all warps done reading stage before refill
    }

    lA += __shfl_xor_sync(0xffffffffu, lA, 1);
    lA += __shfl_xor_sync(0xffffffffu, lA, 2);
    lB += __shfl_xor_sync(0xffffffffu, lB, 1);
    lB += __shfl_xor_sync(0xffffffffu, lB, 2);
    float ivA = 1.f / lA, ivB = 1.f / lB;
    int rowA = b * SQ + w * 16 + r4;
    float* xoA = Xo + (size_t)rowA * DIMSZ + h * HDIM + 2 * q4;
    float* xoB = xoA + 8 * DIMSZ;
#pragma unroll
    for (int dt = 0; dt < 8; dt++) {
        *(float2*)(xoA + dt * 8) = make_float2(o[dt][0] * ivA, o[dt][1] * ivA);
        *(float2*)(xoB + dt * 8) = make_float2(o[dt][2] * ivB, o[dt][3] * ivB);
    }
}

// ---------------------------------------------------------------------------
extern "C" void kernel_launch(void* const* d_in, const int* in_sizes, int n_in,
                              void* d_out, int out_size)
{
    const float* x_q   = (const float*)d_in[0];
    const float* x_k   = (const float*)d_in[1];
    const float* x_v   = (const float*)d_in[2];
    const float* Wq    = (const float*)d_in[3];
    const float* Wk    = (const float*)d_in[4];
    const float* Wv    = (const float*)d_in[5];
    const float* Wproj = (const float*)d_in[6];
    const float* qn_g  = (const float*)d_in[7];
    const float* qn_b  = (const float*)d_in[8];
    const float* kn_g  = (const float*)d_in[9];
    const float* kn_b  = (const float*)d_in[10];
    const float* n_g   = (const float*)d_in[11];
    const float* n_b   = (const float*)d_in[12];
    float* out = (float*)d_out;

    float *Xp;
    __half *Qh, *Kp, *Vp, *xh, *wh, *Xh;
    cudaGetSymbolAddress((void**)&Qh, g_Qh);
    cudaGetSymbolAddress((void**)&Kp, g_K);
    cudaGetSymbolAddress((void**)&Vp, g_V);
    cudaGetSymbolAddress((void**)&Xp, g_X);
    cudaGetSymbolAddress((void**)&xh, g_xh);
    cudaGetSymbolAddress((void**)&wh, g_wh);
    cudaGetSymbolAddress((void**)&Xh, g_Xh);

    static bool attr_set = false;
    if (!attr_set) {
        cudaFuncSetAttribute(gemm_qkv,
                             cudaFuncAttributeMaxDynamicSharedMemorySize, GEMM_SMEM);
        cudaFuncSetAttribute(gemm_proj,
                             cudaFuncAttributeMaxDynamicSharedMemorySize, GEMM_SMEM);
        cudaFuncSetAttribute(attn_mma,
                             cudaFuncAttributeMaxDynamicSharedMemorySize, ATTN_SMEM);
        attr_set = true;
    }

    // fp32 -> fp16 inputs (x_q/x_k/x_v + 4 weights)
    dim3 cvt_grid(BSROWS * DIMSZ / (256 * 8), 7);
    cvt_f2h<<<cvt_grid, 256>>>(x_q, x_k, x_v, Wq, Wk, Wv, Wproj, xh, wh);

    // fused Q/K/V projections + per-head LN (fp16 out) / V fp16 (3-stage pipe)
    dim3 qkv_grid(DIMSZ / 64, BSROWS / 128, 3);
    gemm_qkv<<<qkv_grid, 256, GEMM_SMEM>>>(xh, wh, Qh, Kp, Vp,
                                           qn_g, qn_b, kn_g, kn_b);

    // fused attention (R11 config, fp16 Q)
    attn_mma<<<BSZ * NHEAD, 256, ATTN_SMEM>>>(Qh, Kp, Vp, Xp);

    // output layernorm (fp16 out) + projection
    ln_full<<<BSROWS / 8, 256>>>(Xp, Xh, n_g, n_b);
    dim3 proj_grid(DIMSZ / 64, BSROWS / 128);
    gemm_proj<<<proj_grid, 256, GEMM_SMEM>>>(Xh, wh + 3 * DIMSZ * DIMSZ, out);
}

// round 15
// speedup vs baseline: 2.1663x; 1.0235x over previous
#include <cuda_runtime.h>
#include <cuda_fp16.h>
#include <cstdint>

#define DIMSZ 512
#define NHEAD 8
#define HDIM  64
#define NB    4096
#define BSZ   32
#define SQ    128
#define BSROWS 4096
#define EPSLN 1e-5f

// scratch (allocation-free rule: __device__ globals)
__device__ __half g_xh[3 * BSROWS * DIMSZ];   // x_q, x_k, x_v in fp16
__device__ __half g_wh[4 * DIMSZ * DIMSZ];    // Wq, Wk, Wv, Wproj in fp16
__device__ __half g_Qh[BSROWS * DIMSZ];
__device__ __half g_K[NB * DIMSZ];
__device__ __half g_V[NB * DIMSZ];
__device__ float  g_X[BSROWS * DIMSZ];
__device__ __half g_Xh[BSROWS * DIMSZ];

// ---------------------------------------------------------------------------
// helpers
// ---------------------------------------------------------------------------
__device__ __forceinline__ void mma_f16(
    float& c0, float& c1, float& c2, float& c3,
    unsigned a0, unsigned a1, unsigned a2, unsigned a3,
    unsigned b0, unsigned b1)
{
    asm volatile(
        "mma.sync.aligned.m16n8k16.row.col.f32.f16.f16.f32 "
        "{%0,%1,%2,%3}, {%4,%5,%6,%7}, {%8,%9}, {%0,%1,%2,%3};"
        : "+f"(c0), "+f"(c1), "+f"(c2), "+f"(c3)
        : "r"(a0), "r"(a1), "r"(a2), "r"(a3), "r"(b0), "r"(b1));
}
__device__ __forceinline__ unsigned f16x2_of(float lo, float hi) {
    unsigned d;
    asm("cvt.rn.f16x2.f32 %0, %1, %2;" : "=r"(d) : "f"(hi), "f"(lo));
    return d;
}
__device__ __forceinline__ void ldsm4(
    unsigned& r0, unsigned& r1, unsigned& r2, unsigned& r3, uint32_t addr)
{
    asm volatile(
        "ldmatrix.sync.aligned.m8n8.x4.shared.b16 {%0,%1,%2,%3}, [%4];"
        : "=r"(r0), "=r"(r1), "=r"(r2), "=r"(r3) : "r"(addr));
}
__device__ __forceinline__ void ldsm4t(
    unsigned& r0, unsigned& r1, unsigned& r2, unsigned& r3, uint32_t addr)
{
    asm volatile(
        "ldmatrix.sync.aligned.m8n8.x4.trans.shared.b16 {%0,%1,%2,%3}, [%4];"
        : "=r"(r0), "=r"(r1), "=r"(r2), "=r"(r3) : "r"(addr));
}
__device__ __forceinline__ void cpa16(uint32_t s, const void* g) {
    asm volatile("cp.async.cg.shared.global [%0], [%1], 16;" :: "r"(s), "l"(g));
}
__device__ __forceinline__ void cpa_commit() { asm volatile("cp.async.commit_group;"); }
__device__ __forceinline__ void cpa_wait1()  { asm volatile("cp.async.wait_group 1;"); }
__device__ __forceinline__ void cpa_wait0()  { asm volatile("cp.async.wait_group 0;"); }

// ---------------------------------------------------------------------------
// fp32 -> fp16 conversion pass for x_q/x_k/x_v (z=0..2) and W's (z=3..6)
// ---------------------------------------------------------------------------
__global__ __launch_bounds__(256) void cvt_f2h(
    const float* __restrict__ x_q, const float* __restrict__ x_k,
    const float* __restrict__ x_v,
    const float* __restrict__ Wq, const float* __restrict__ Wk,
    const float* __restrict__ Wv, const float* __restrict__ Wp,
    __half* __restrict__ xh, __half* __restrict__ wh)
{
    int z = blockIdx.y;
    const float* s;
    __half* d;
    int n;
    if (z < 3) {
        s = (z == 0) ? x_q : (z == 1) ? x_k : x_v;
        d = xh + (size_t)z * BSROWS * DIMSZ;
        n = BSROWS * DIMSZ;
    } else {
        int zz = z - 3;
        s = (zz == 0) ? Wq : (zz == 1) ? Wk : (zz == 2) ? Wv : Wp;
        d = wh + (size_t)zz * DIMSZ * DIMSZ;
        n = DIMSZ * DIMSZ;
    }
    int idx = (blockIdx.x * 256 + threadIdx.x) * 8;
    if (idx >= n) return;
    float4 a = *(const float4*)(s + idx);
    float4 b = *(const float4*)(s + idx + 4);
    *(uint4*)(d + idx) = make_uint4(
        f16x2_of(a.x, a.y), f16x2_of(a.z, a.w),
        f16x2_of(b.x, b.y), f16x2_of(b.z, b.w));
}

// ---------------------------------------------------------------------------
// fp16 GEMM (fp32 accumulate), 3-stage cp.async pipeline, ONE sync per k-tile.
// (unchanged from R14)
// ---------------------------------------------------------------------------
#define GHS 72
#define ABUF (128 * GHS)
#define BBUF (64 * GHS)
#define NKT  (DIMSZ / 64)                   // 8 k-tiles
#define GEMM_SMEM ((3 * ABUF + 3 * BBUF) * 2)

__device__ __forceinline__ void gemm_fill(
    uint32_t smem_u, int stage,
    const __half* __restrict__ A, const __half* __restrict__ Bw,
    int bm, int bn, int kt,
    const int* arow, const int* brow, int hg)
{
#pragma unroll
    for (int i = 0; i < 4; i++)
        cpa16(smem_u + (uint32_t)(stage * ABUF + arow[i] * GHS + hg) * 2,
              A + (size_t)(bm + arow[i]) * DIMSZ + kt + hg);
#pragma unroll
    for (int i = 0; i < 2; i++)
        cpa16(smem_u + (uint32_t)(3 * ABUF + stage * BBUF + brow[i] * GHS + hg) * 2,
              Bw + (size_t)(bn + brow[i]) * DIMSZ + kt + hg);
    cpa_commit();
}

__device__ __forceinline__ void gemm_body(
    const __half* __restrict__ A, const __half* __restrict__ Bw,
    float* __restrict__ C, __half* __restrict__ Ch,
    int bm, int bn, int mode,
    const float* __restrict__ lng, const float* __restrict__ lnb, float lscale)
{
    extern __shared__ __half gsmh[];   // [A0][A1][A2][B0][B1][B2]
    float* red = (float*)gsmh;         // LN reduce buffer aliases A0 in epilogue
    const uint32_t smem_u = (uint32_t)__cvta_generic_to_shared(gsmh);

    const int tid = threadIdx.x;
    const int lane = tid & 31, w = tid >> 5;
    const int q4 = lane & 3, r4 = lane >> 2;
    const int wm = (w & 3) * 32;
    const int wn = (w >> 2);
    const int wncol = wn * 32;

    const int arow[4] = { (tid + 0) >> 3, (tid + 256) >> 3, (tid + 512) >> 3, (tid + 768) >> 3 };
    const int brow[2] = { (tid + 0) >> 3, (tid + 256) >> 3 };
    const int hg = (tid & 7) * 8;

    const int lm_mat = lane >> 3, lm_r = lane & 7;
    const uint32_t alm_off =
        (uint32_t)(((wm + (lm_mat & 1) * 8 + lm_r) * GHS) + (lm_mat >> 1) * 8) * 2;
    const uint32_t blm_off = (uint32_t)(3 * ABUF) * 2 +
        (uint32_t)(((wncol + (lm_mat >> 1) * 8 + lm_r) * GHS) + (lm_mat & 1) * 8) * 2;

    // prologue: stages 0 and 1
    gemm_fill(smem_u, 0, A, Bw, bm, bn, 0, arow, brow, hg);
    gemm_fill(smem_u, 1, A, Bw, bm, bn, 64, arow, brow, hg);

    float acc[2][4][4];
#pragma unroll
    for (int mt = 0; mt < 2; mt++)
#pragma unroll
        for (int nt = 0; nt < 4; nt++)
#pragma unroll
            for (int c = 0; c < 4; c++) acc[mt][nt][c] = 0.f;

    for (int t = 0; t < NKT; t++) {
        int st = t % 3;
        if (t + 1 < NKT) cpa_wait1(); else cpa_wait0();
        __syncthreads();
        if (t + 2 < NKT)
            gemm_fill(smem_u, (t + 2) % 3, A, Bw, bm, bn, (t + 2) * 64, arow, brow, hg);

        const uint32_t abase = alm_off + (uint32_t)(st * ABUF) * 2 + smem_u;
        const uint32_t bbase = blm_off + (uint32_t)(st * BBUF) * 2 + smem_u;
#pragma unroll
        for (int kk = 0; kk < 4; kk++) {
            unsigned af[2][4];
#pragma unroll
            for (int mt = 0; mt < 2; mt++)
                ldsm4(af[mt][0], af[mt][1], af[mt][2], af[mt][3],
                      abase + (uint32_t)(mt * 16 * GHS + kk * 16) * 2);
#pragma unroll
            for (int nt2 = 0; nt2 < 2; nt2++) {
                unsigned b0, b1, b2, b3;
                ldsm4(b0, b1, b2, b3,
                      bbase + (uint32_t)(nt2 * 16 * GHS + kk * 16) * 2);
#pragma unroll
                for (int mt = 0; mt < 2; mt++) {
                    mma_f16(acc[mt][2 * nt2][0], acc[mt][2 * nt2][1],
                            acc[mt][2 * nt2][2], acc[mt][2 * nt2][3],
                            af[mt][0], af[mt][1], af[mt][2], af[mt][3], b0, b1);
                    mma_f16(acc[mt][2 * nt2 + 1][0], acc[mt][2 * nt2 + 1][1],
                            acc[mt][2 * nt2 + 1][2], acc[mt][2 * nt2 + 1][3],
                            af[mt][0], af[mt][1], af[mt][2], af[mt][3], b2, b3);
                }
            }
        }
    }

    if (mode == 1 || mode == 3) {
        // -------- fused per-head layernorm (fp16 out) --------
        __syncthreads();
#pragma unroll
        for (int mt = 0; mt < 2; mt++) {
#pragma unroll
            for (int half = 0; half < 2; half++) {
                float s = 0.f, ss = 0.f;
#pragma unroll
                for (int nt = 0; nt < 4; nt++) {
                    float v0 = acc[mt][nt][2 * half];
                    float v1 = acc[mt][nt][2 * half + 1];
                    s += v0 + v1;
                    ss += v0 * v0 + v1 * v1;
                }
                s += __shfl_xor_sync(0xffffffffu, s, 1);
                s += __shfl_xor_sync(0xffffffffu, s, 2);
                ss += __shfl_xor_sync(0xffffffffu, ss, 1);
                ss += __shfl_xor_sync(0xffffffffu, ss, 2);
                if (q4 == 0) {
                    int row = wm + mt * 16 + half * 8 + r4;
                    red[(wn * 128 + row) * 2 + 0] = s;
                    red[(wn * 128 + row) * 2 + 1] = ss;
                }
            }
        }
        __syncthreads();
#pragma unroll
        for (int mt = 0; mt < 2; mt++) {
#pragma unroll
            for (int half = 0; half < 2; half++) {
                int row = wm + mt * 16 + half * 8 + r4;
                float S  = red[row * 2 + 0] + red[(128 + row) * 2 + 0];
                float SS = red[row * 2 + 1] + red[(128 + row) * 2 + 1];
                float m = S * (1.f / 64.f);
                float var = SS * (1.f / 64.f) - m * m;
                float rr = rsqrtf(var + EPSLN);
#pragma unroll
                for (int nt = 0; nt < 4; nt++) {
                    int ci = wncol + nt * 8 + 2 * q4;
                    float o0 = ((acc[mt][nt][2 * half]     - m) * rr * lng[ci]     + lnb[ci])     * lscale;
                    float o1 = ((acc[mt][nt][2 * half + 1] - m) * rr * lng[ci + 1] + lnb[ci + 1]) * lscale;
                    __half* cp = Ch + (size_t)(bm + row) * DIMSZ + bn + ci;
                    *(__half2*)cp = __floats2half2_rn(o0, o1);
                }
            }
        }
    } else if (mode == 2) {
#pragma unroll
        for (int mt = 0; mt < 2; mt++) {
            int r0 = bm + wm + mt * 16 + r4;
#pragma unroll
            for (int nt = 0; nt < 4; nt++) {
                __half* cp = Ch + (size_t)r0 * DIMSZ + bn + wncol + nt * 8 + 2 * q4;
                *(__half2*)cp = __floats2half2_rn(acc[mt][nt][0], acc[mt][nt][1]);
                *(__half2*)(cp + (size_t)8 * DIMSZ) =
                    __floats2half2_rn(acc[mt][nt][2], acc[mt][nt][3]);
            }
        }
    } else {
#pragma unroll
        for (int mt = 0; mt < 2; mt++) {
            int r0 = bm + wm + mt * 16 + r4;
#pragma unroll
            for (int nt = 0; nt < 4; nt++) {
                float* cp = C + (size_t)r0 * DIMSZ + bn + wncol + nt * 8 + 2 * q4;
                *(float2*)cp = make_float2(acc[mt][nt][0], acc[mt][nt][1]);
                *(float2*)(cp + (size_t)8 * DIMSZ) =
                    make_float2(acc[mt][nt][2], acc[mt][nt][3]);
            }
        }
    }
}

__global__ __launch_bounds__(256, 2) void gemm_qkv(
    const __half* __restrict__ xh, const __half* __restrict__ wh,
    __half* __restrict__ Qh, __half* __restrict__ Kp, __half* __restrict__ Vp,
    const float* __restrict__ qg, const float* __restrict__ qb,
    const float* __restrict__ kg, const float* __restrict__ kb)
{
    const int z = blockIdx.z;
    const __half* A  = xh + (size_t)z * BSROWS * DIMSZ;
    const __half* Bw = wh + (size_t)z * DIMSZ * DIMSZ;
    __half* Ch      = (z == 0) ? Qh : (z == 1) ? Kp : Vp;
    const float* g  = (z == 0) ? qg : kg;
    const float* bb = (z == 0) ? qb : kb;
    float sc        = (z == 0) ? 0.125f : 1.0f;
    int mode        = (z == 0) ? 1 : (z == 1) ? 3 : 2;
    gemm_body(A, Bw, nullptr, Ch, blockIdx.y * 128, blockIdx.x * 64, mode, g, bb, sc);
}

__global__ __launch_bounds__(256, 2) void gemm_proj(
    const __half* __restrict__ A, const __half* __restrict__ Bw, float* __restrict__ C)
{
    gemm_body(A, Bw, C, nullptr, blockIdx.y * 128, blockIdx.x * 64, 0, nullptr, nullptr, 1.f);
}

// ---------------------------------------------------------------------------
// Full-row layernorm over D=512: fp32 in, fp16 out. One warp per row.
// ---------------------------------------------------------------------------
__global__ __launch_bounds__(256) void ln_full(
    const float* __restrict__ X, __half* __restrict__ Xh,
    const float* __restrict__ g, const float* __restrict__ bb)
{
    int row = blockIdx.x * 8 + (threadIdx.x >> 5);
    int lane = threadIdx.x & 31;
    const float* p = X + (size_t)row * DIMSZ;
    float4 x[4];
    float s = 0.f;
#pragma unroll
    for (int q = 0; q < 4; q++) {
        x[q] = *(const float4*)(p + lane * 4 + q * 128);
        s += x[q].x + x[q].y + x[q].z + x[q].w;
    }
#pragma unroll
    for (int off = 16; off; off >>= 1) s += __shfl_xor_sync(0xffffffffu, s, off);
    float m = s * (1.f / 512.f);
    float v = 0.f;
#pragma unroll
    for (int q = 0; q < 4; q++) {
        x[q].x -= m; x[q].y -= m; x[q].z -= m; x[q].w -= m;
        v += x[q].x * x[q].x + x[q].y * x[q].y + x[q].z * x[q].z + x[q].w * x[q].w;
    }
#pragma unroll
    for (int off = 16; off; off >>= 1) v += __shfl_xor_sync(0xffffffffu, v, off);
    float r = rsqrtf(v * (1.f / 512.f) + EPSLN);
#pragma unroll
    for (int q = 0; q < 4; q++) {
        int c = lane * 4 + q * 128;
        float4 gg = *(const float4*)(g + c);
        float4 bv = *(const float4*)(bb + c);
        uint2 st = make_uint2(
            f16x2_of(x[q].x * r * gg.x + bv.x, x[q].y * r * gg.y + bv.y),
            f16x2_of(x[q].z * r * gg.z + bv.z, x[q].w * r * gg.w + bv.w));
        *(uint2*)(Xh + (size_t)row * DIMSZ + c) = st;
    }
}

// ---------------------------------------------------------------------------
// Fused flash attention: fp16 operands, fixed-max softmax, cp.async
// double-buffered K/V in 128-key stages, ONE barrier per stage.
// With 2 stages, (t+1)&1 == (t-1)&1: issuing fill(t+1) AFTER the barrier of
// iter t makes the target buffer provably idle -> trailing barrier removed.
// One block per (b,h). 256 threads = 8 warps, 16 query rows per warp.
// ---------------------------------------------------------------------------
#define HSTR 72
#define KVS (128 * HSTR)                 // halves per stage per tensor
#define ATTN_SMEM (4 * KVS * 2)          // K0 K1 V0 V1, bytes
#define NSTG (NB / 128)                  // 32 stages
#define PEXPC 7.2134752f                 // 5.0 * log2(e)

__global__ __launch_bounds__(256, 2) void attn_mma(
    const __half* __restrict__ Qh, const __half* __restrict__ Kb,
    const __half* __restrict__ Vb, float* __restrict__ Xo)
{
    extern __shared__ __half asm_h[];    // [K st0][K st1][V st0][V st1]
    const uint32_t sm_u = (uint32_t)__cvta_generic_to_shared(asm_h);

    const int bh = blockIdx.x;
    const int b = bh >> 3, h = bh & 7;
    const int tid = threadIdx.x;
    const int w = tid >> 5, lane = tid & 31;
    const int q4 = lane & 3, r4 = lane >> 2;

    const __half* kbase = Kb + h * HDIM;
    const __half* vbase = Vb + h * HDIM;

    // fill coords: 4 chunks of 16B per tensor per thread per stage
    int cj[4];
    const int chg = (tid & 7) * 8;
#pragma unroll
    for (int i = 0; i < 4; i++) cj[i] = (tid + i * 256) >> 3;   // key 0..127

    const int lm_mat = lane >> 3, lm_r = lane & 7;
    const uint32_t klm_off =
        (uint32_t)(((lm_mat >> 1) * 8 + lm_r) * HSTR + (lm_mat & 1) * 8) * 2;
    const uint32_t vlm_off =
        (uint32_t)(((lm_mat & 1) * 8 + lm_r) * HSTR + (lm_mat >> 1) * 8) * 2;

    // issue stage 0
#pragma unroll
    for (int i = 0; i < 4; i++) {
        cpa16(sm_u + (uint32_t)(cj[i] * HSTR + chg) * 2,
              kbase + (size_t)cj[i] * DIMSZ + chg);
        cpa16(sm_u + (uint32_t)(2 * KVS + cj[i] * HSTR + chg) * 2,
              vbase + (size_t)cj[i] * DIMSZ + chg);
    }
    cpa_commit();

    // Q fragments: fp16 in gmem, adjacent pairs -> direct 32-bit loads
    unsigned qa[4][4];
    {
        const __half* q0 = Qh + (size_t)(b * SQ + w * 16 + r4) * DIMSZ + h * HDIM;
        const __half* q1 = q0 + 8 * DIMSZ;
#pragma unroll
        for (int kk = 0; kk < 4; kk++) {
            int col = kk * 16 + 2 * q4;
            qa[kk][0] = *(const unsigned*)(q0 + col);
            qa[kk][1] = *(const unsigned*)(q1 + col);
            qa[kk][2] = *(const unsigned*)(q0 + col + 8);
            qa[kk][3] = *(const unsigned*)(q1 + col + 8);
        }
    }

    float lA = 0.f, lB = 0.f;
    float o[8][4];
#pragma unroll
    for (int dt = 0; dt < 8; dt++)
        o[dt][0] = o[dt][1] = o[dt][2] = o[dt][3] = 0.f;

    for (int t = 0; t < NSTG; t++) {
        int st = t & 1;
        cpa_wait0();            // only fill(t) outstanding
        __syncthreads();        // fill(t) visible to all; compute(t-1) done by all
        if (t + 1 < NSTG) {     // fill buffer (t+1)&1 == (t-1)&1: idle
            int n1 = (t + 1) * 128;
            int ns = st ^ 1;
#pragma unroll
            for (int i = 0; i < 4; i++) {
                cpa16(sm_u + (uint32_t)(ns * KVS + cj[i] * HSTR + chg) * 2,
                      kbase + (size_t)(n1 + cj[i]) * DIMSZ + chg);
                cpa16(sm_u + (uint32_t)(2 * KVS + ns * KVS + cj[i] * HSTR + chg) * 2,
                      vbase + (size_t)(n1 + cj[i]) * DIMSZ + chg);
            }
            cpa_commit();
        }

#pragma unroll
        for (int sub = 0; sub < 2; sub++) {
            const uint32_t kbb = sm_u + (uint32_t)(st * KVS + sub * 64 * HSTR) * 2 + klm_off;
            const uint32_t vbb = sm_u + (uint32_t)(2 * KVS + st * KVS + sub * 64 * HSTR) * 2 + vlm_off;

            // ---- scores: S = Q K^T ----
            float s[8][4];
#pragma unroll
            for (int nt = 0; nt < 8; nt++)
                s[nt][0] = s[nt][1] = s[nt][2] = s[nt][3] = 0.f;
#pragma unroll
            for (int kk = 0; kk < 4; kk++) {
#pragma unroll
                for (int nt2 = 0; nt2 < 4; nt2++) {
                    unsigned b0, b1, b2, b3;
                    ldsm4(b0, b1, b2, b3,
                          kbb + (uint32_t)(nt2 * 16 * HSTR + kk * 16) * 2);
                    mma_f16(s[2 * nt2][0], s[2 * nt2][1], s[2 * nt2][2], s[2 * nt2][3],
                            qa[kk][0], qa[kk][1], qa[kk][2], qa[kk][3], b0, b1);
                    mma_f16(s[2 * nt2 + 1][0], s[2 * nt2 + 1][1], s[2 * nt2 + 1][2], s[2 * nt2 + 1][3],
                            qa[kk][0], qa[kk][1], qa[kk][2], qa[kk][3], b2, b3);
                }
            }

            // ---- fixed-max softmax; pack P into fp16 A-fragments ----
            float suA = 0.f, suB = 0.f;
            unsigned ph[4][4];
#pragma unroll
            for (int nt = 0; nt < 8; nt++) {
                float p0 = exp2f(fmaf(s[nt][0], 1.44269504f, -PEXPC));
                float p1 = exp2f(fmaf(s[nt][1], 1.44269504f, -PEXPC));
                float p2 = exp2f(fmaf(s[nt][2], 1.44269504f, -PEXPC));
                float p3 = exp2f(fmaf(s[nt][3], 1.44269504f, -PEXPC));
                suA += p0 + p1; suB += p2 + p3;
                int tt = nt >> 1;
                if ((nt & 1) == 0) {
                    ph[tt][0] = f16x2_of(p0, p1);
                    ph[tt][1] = f16x2_of(p2, p3);
                } else {
                    ph[tt][2] = f16x2_of(p0, p1);
                    ph[tt][3] = f16x2_of(p2, p3);
                }
            }
            lA += suA;
            lB += suB;

            // ---- O += P @ V ----
#pragma unroll
            for (int kk = 0; kk < 4; kk++) {
#pragma unroll
                for (int dt2 = 0; dt2 < 4; dt2++) {
                    unsigned v0, v1, v2, v3;
                    ldsm4t(v0, v1, v2, v3,
                           vbb + (uint32_t)(kk * 16 * HSTR + dt2 * 16) * 2);
                    mma_f16(o[2 * dt2][0], o[2 * dt2][1], o[2 * dt2][2], o[2 * dt2][3],
                            ph[kk][0], ph[kk][1], ph[kk][2], ph[kk][3], v0, v1);
                    mma_f16(o[2 * dt2 + 1][0], o[2 * dt2 + 1][1], o[2 * dt2 + 1][2], o[2 * dt2 + 1][3],
                            ph[kk][0], ph[kk][1], ph[kk][2], ph[kk][3], v2, v3);
                }
            }
        }
    }

    lA += __shfl_xor_sync(0xffffffffu, lA, 1);
    lA += __shfl_xor_sync(0xffffffffu, lA, 2);
    lB += __shfl_xor_sync(0xffffffffu, lB, 1);
    lB += __shfl_xor_sync(0xffffffffu, lB, 2);
    float ivA = 1.f / lA, ivB = 1.f / lB;
    int rowA = b * SQ + w * 16 + r4;
    float* xoA = Xo + (size_t)rowA * DIMSZ + h * HDIM + 2 * q4;
    float* xoB = xoA + 8 * DIMSZ;
#pragma unroll
    for (int dt = 0; dt < 8; dt++) {
        *(float2*)(xoA + dt * 8) = make_float2(o[dt][0] * ivA, o[dt][1] * ivA);
        *(float2*)(xoB + dt * 8) = make_float2(o[dt][2] * ivB, o[dt][3] * ivB);
    }
}

// ---------------------------------------------------------------------------
extern "C" void kernel_launch(void* const* d_in, const int* in_sizes, int n_in,
                              void* d_out, int out_size)
{
    const float* x_q   = (const float*)d_in[0];
    const float* x_k   = (const float*)d_in[1];
    const float* x_v   = (const float*)d_in[2];
    const float* Wq    = (const float*)d_in[3];
    const float* Wk    = (const float*)d_in[4];
    const float* Wv    = (const float*)d_in[5];
    const float* Wproj = (const float*)d_in[6];
    const float* qn_g  = (const float*)d_in[7];
    const float* qn_b  = (const float*)d_in[8];
    const float* kn_g  = (const float*)d_in[9];
    const float* kn_b  = (const float*)d_in[10];
    const float* n_g   = (const float*)d_in[11];
    const float* n_b   = (const float*)d_in[12];
    float* out = (float*)d_out;

    float *Xp;
    __half *Qh, *Kp, *Vp, *xh, *wh, *Xh;
    cudaGetSymbolAddress((void**)&Qh, g_Qh);
    cudaGetSymbolAddress((void**)&Kp, g_K);
    cudaGetSymbolAddress((void**)&Vp, g_V);
    cudaGetSymbolAddress((void**)&Xp, g_X);
    cudaGetSymbolAddress((void**)&xh, g_xh);
    cudaGetSymbolAddress((void**)&wh, g_wh);
    cudaGetSymbolAddress((void**)&Xh, g_Xh);

    static bool attr_set = false;
    if (!attr_set) {
        cudaFuncSetAttribute(gemm_qkv,
                             cudaFuncAttributeMaxDynamicSharedMemorySize, GEMM_SMEM);
        cudaFuncSetAttribute(gemm_proj,
                             cudaFuncAttributeMaxDynamicSharedMemorySize, GEMM_SMEM);
        cudaFuncSetAttribute(attn_mma,
                             cudaFuncAttributeMaxDynamicSharedMemorySize, ATTN_SMEM);
        attr_set = true;
    }

    // fp32 -> fp16 inputs (x_q/x_k/x_v + 4 weights)
    dim3 cvt_grid(BSROWS * DIMSZ / (256 * 8), 7);
    cvt_f2h<<<cvt_grid, 256>>>(x_q, x_k, x_v, Wq, Wk, Wv, Wproj, xh, wh);

    // fused Q/K/V projections + per-head LN (fp16 out) / V fp16 (3-stage pipe)
    dim3 qkv_grid(DIMSZ / 64, BSROWS / 128, 3);
    gemm_qkv<<<qkv_grid, 256, GEMM_SMEM>>>(xh, wh, Qh, Kp, Vp,
                                           qn_g, qn_b, kn_g, kn_b);

    // fused attention (single barrier per K/V stage)
    attn_mma<<<BSZ * NHEAD, 256, ATTN_SMEM>>>(Qh, Kp, Vp, Xp);

    // output layernorm (fp16 out) + projection
    ln_full<<<BSROWS / 8, 256>>>(Xp, Xh, n_g, n_b);
    dim3 proj_grid(DIMSZ / 64, BSROWS / 128);
    gemm_proj<<<proj_grid, 256, GEMM_SMEM>>>(Xh, wh + 3 * DIMSZ * DIMSZ, out);
}

// round 16
// speedup vs baseline: 2.2753x; 1.0503x over previous
#include <cuda_runtime.h>
#include <cuda.h>
#include <cuda_fp16.h>
#include <cstdint>

#define DIMSZ 512
#define NHEAD 8
#define HDIM  64
#define NB    4096
#define BSZ   32
#define SQ    128
#define BSROWS 4096
#define EPSLN 1e-5f

// scratch (allocation-free rule: __device__ globals)
__device__ __half g_xh[3 * BSROWS * DIMSZ];   // x_q, x_k, x_v in fp16
__device__ __half g_wh[4 * DIMSZ * DIMSZ];    // Wq, Wk, Wv, Wproj in fp16
__device__ __half g_Qh[BSROWS * DIMSZ];
__device__ __half g_K[NB * DIMSZ];
__device__ __half g_V[NB * DIMSZ];
__device__ float  g_X[BSROWS * DIMSZ];
__device__ __half g_Xh[BSROWS * DIMSZ];

// ---------------------------------------------------------------------------
// helpers
// ---------------------------------------------------------------------------
__device__ __forceinline__ void mma_f16(
    float& c0, float& c1, float& c2, float& c3,
    unsigned a0, unsigned a1, unsigned a2, unsigned a3,
    unsigned b0, unsigned b1)
{
    asm volatile(
        "mma.sync.aligned.m16n8k16.row.col.f32.f16.f16.f32 "
        "{%0,%1,%2,%3}, {%4,%5,%6,%7}, {%8,%9}, {%0,%1,%2,%3};"
        : "+f"(c0), "+f"(c1), "+f"(c2), "+f"(c3)
        : "r"(a0), "r"(a1), "r"(a2), "r"(a3), "r"(b0), "r"(b1));
}
__device__ __forceinline__ unsigned f16x2_of(float lo, float hi) {
    unsigned d;
    asm("cvt.rn.f16x2.f32 %0, %1, %2;" : "=r"(d) : "f"(hi), "f"(lo));
    return d;
}
__device__ __forceinline__ void ldsm4(
    unsigned& r0, unsigned& r1, unsigned& r2, unsigned& r3, uint32_t addr)
{
    asm volatile(
        "ldmatrix.sync.aligned.m8n8.x4.shared.b16 {%0,%1,%2,%3}, [%4];"
        : "=r"(r0), "=r"(r1), "=r"(r2), "=r"(r3) : "r"(addr));
}
__device__ __forceinline__ void ldsm4t(
    unsigned& r0, unsigned& r1, unsigned& r2, unsigned& r3, uint32_t addr)
{
    asm volatile(
        "ldmatrix.sync.aligned.m8n8.x4.trans.shared.b16 {%0,%1,%2,%3}, [%4];"
        : "=r"(r0), "=r"(r1), "=r"(r2), "=r"(r3) : "r"(addr));
}
__device__ __forceinline__ void cpa16(uint32_t s, const void* g) {
    asm volatile("cp.async.cg.shared.global [%0], [%1], 16;" :: "r"(s), "l"(g));
}
__device__ __forceinline__ void cpa_commit() { asm volatile("cp.async.commit_group;"); }
__device__ __forceinline__ void cpa_wait1()  { asm volatile("cp.async.wait_group 1;"); }
__device__ __forceinline__ void cpa_wait0()  { asm volatile("cp.async.wait_group 0;"); }

// mbarrier / TMA helpers
__device__ __forceinline__ void mbar_init(uint32_t a, uint32_t cnt) {
    asm volatile("mbarrier.init.shared.b64 [%0], %1;" :: "r"(a), "r"(cnt) : "memory");
}
__device__ __forceinline__ void mbar_expect(uint32_t a, uint32_t bytes) {
    asm volatile("mbarrier.arrive.expect_tx.shared.b64 _, [%0], %1;"
                 :: "r"(a), "r"(bytes) : "memory");
}
__device__ __forceinline__ void mbar_wait(uint32_t a, uint32_t ph) {
    asm volatile(
        "{\n\t.reg .pred P;\n"
        "LW%=:\n\t"
        "mbarrier.try_wait.parity.acquire.cta.shared::cta.b64 P, [%0], %1;\n\t"
        "@P bra.uni LD%=;\n\t"
        "bra.uni LW%=;\n"
        "LD%=:\n\t}"
        :: "r"(a), "r"(ph) : "memory");
}
__device__ __forceinline__ void tma2d(
    uint32_t saddr, const void* map, int cx, int cy, uint32_t mbar)
{
    asm volatile(
        "cp.async.bulk.tensor.2d.shared::cta.global.tile.mbarrier::complete_tx::bytes "
        "[%0], [%1, {%2, %3}], [%4];"
        :: "r"(saddr), "l"(map), "r"(cx), "r"(cy), "r"(mbar) : "memory");
}

// ---------------------------------------------------------------------------
// fp32 -> fp16 conversion pass for x_q/x_k/x_v (z=0..2) and W's (z=3..6)
// ---------------------------------------------------------------------------
__global__ __launch_bounds__(256) void cvt_f2h(
    const float* __restrict__ x_q, const float* __restrict__ x_k,
    const float* __restrict__ x_v,
    const float* __restrict__ Wq, const float* __restrict__ Wk,
    const float* __restrict__ Wv, const float* __restrict__ Wp,
    __half* __restrict__ xh, __half* __restrict__ wh)
{
    int z = blockIdx.y;
    const float* s;
    __half* d;
    int n;
    if (z < 3) {
        s = (z == 0) ? x_q : (z == 1) ? x_k : x_v;
        d = xh + (size_t)z * BSROWS * DIMSZ;
        n = BSROWS * DIMSZ;
    } else {
        int zz = z - 3;
        s = (zz == 0) ? Wq : (zz == 1) ? Wk : (zz == 2) ? Wv : Wp;
        d = wh + (size_t)zz * DIMSZ * DIMSZ;
        n = DIMSZ * DIMSZ;
    }
    int idx = (blockIdx.x * 256 + threadIdx.x) * 8;
    if (idx >= n) return;
    float4 a = *(const float4*)(s + idx);
    float4 b = *(const float4*)(s + idx + 4);
    *(uint4*)(d + idx) = make_uint4(
        f16x2_of(a.x, a.y), f16x2_of(a.z, a.w),
        f16x2_of(b.x, b.y), f16x2_of(b.z, b.w));
}

// ---------------------------------------------------------------------------
// fp16 GEMM (fp32 accumulate), 3-stage cp.async pipeline. (unchanged, R15)
// ---------------------------------------------------------------------------
#define GHS 72
#define ABUF (128 * GHS)
#define BBUF (64 * GHS)
#define NKT  (DIMSZ / 64)
#define GEMM_SMEM ((3 * ABUF + 3 * BBUF) * 2)

__device__ __forceinline__ void gemm_fill(
    uint32_t smem_u, int stage,
    const __half* __restrict__ A, const __half* __restrict__ Bw,
    int bm, int bn, int kt,
    const int* arow, const int* brow, int hg)
{
#pragma unroll
    for (int i = 0; i < 4; i++)
        cpa16(smem_u + (uint32_t)(stage * ABUF + arow[i] * GHS + hg) * 2,
              A + (size_t)(bm + arow[i]) * DIMSZ + kt + hg);
#pragma unroll
    for (int i = 0; i < 2; i++)
        cpa16(smem_u + (uint32_t)(3 * ABUF + stage * BBUF + brow[i] * GHS + hg) * 2,
              Bw + (size_t)(bn + brow[i]) * DIMSZ + kt + hg);
    cpa_commit();
}

__device__ __forceinline__ void gemm_body(
    const __half* __restrict__ A, const __half* __restrict__ Bw,
    float* __restrict__ C, __half* __restrict__ Ch,
    int bm, int bn, int mode,
    const float* __restrict__ lng, const float* __restrict__ lnb, float lscale)
{
    extern __shared__ __half gsmh[];
    float* red = (float*)gsmh;
    const uint32_t smem_u = (uint32_t)__cvta_generic_to_shared(gsmh);

    const int tid = threadIdx.x;
    const int lane = tid & 31, w = tid >> 5;
    const int q4 = lane & 3, r4 = lane >> 2;
    const int wm = (w & 3) * 32;
    const int wn = (w >> 2);
    const int wncol = wn * 32;

    const int arow[4] = { (tid + 0) >> 3, (tid + 256) >> 3, (tid + 512) >> 3, (tid + 768) >> 3 };
    const int brow[2] = { (tid + 0) >> 3, (tid + 256) >> 3 };
    const int hg = (tid & 7) * 8;

    const int lm_mat = lane >> 3, lm_r = lane & 7;
    const uint32_t alm_off =
        (uint32_t)(((wm + (lm_mat & 1) * 8 + lm_r) * GHS) + (lm_mat >> 1) * 8) * 2;
    const uint32_t blm_off = (uint32_t)(3 * ABUF) * 2 +
        (uint32_t)(((wncol + (lm_mat >> 1) * 8 + lm_r) * GHS) + (lm_mat & 1) * 8) * 2;

    gemm_fill(smem_u, 0, A, Bw, bm, bn, 0, arow, brow, hg);
    gemm_fill(smem_u, 1, A, Bw, bm, bn, 64, arow, brow, hg);

    float acc[2][4][4];
#pragma unroll
    for (int mt = 0; mt < 2; mt++)
#pragma unroll
        for (int nt = 0; nt < 4; nt++)
#pragma unroll
            for (int c = 0; c < 4; c++) acc[mt][nt][c] = 0.f;

    for (int t = 0; t < NKT; t++) {
        int st = t % 3;
        if (t + 1 < NKT) cpa_wait1(); else cpa_wait0();
        __syncthreads();
        if (t + 2 < NKT)
            gemm_fill(smem_u, (t + 2) % 3, A, Bw, bm, bn, (t + 2) * 64, arow, brow, hg);

        const uint32_t abase = alm_off + (uint32_t)(st * ABUF) * 2 + smem_u;
        const uint32_t bbase = blm_off + (uint32_t)(st * BBUF) * 2 + smem_u;
#pragma unroll
        for (int kk = 0; kk < 4; kk++) {
            unsigned af[2][4];
#pragma unroll
            for (int mt = 0; mt < 2; mt++)
                ldsm4(af[mt][0], af[mt][1], af[mt][2], af[mt][3],
                      abase + (uint32_t)(mt * 16 * GHS + kk * 16) * 2);
#pragma unroll
            for (int nt2 = 0; nt2 < 2; nt2++) {
                unsigned b0, b1, b2, b3;
                ldsm4(b0, b1, b2, b3,
                      bbase + (uint32_t)(nt2 * 16 * GHS + kk * 16) * 2);
#pragma unroll
                for (int mt = 0; mt < 2; mt++) {
                    mma_f16(acc[mt][2 * nt2][0], acc[mt][2 * nt2][1],
                            acc[mt][2 * nt2][2], acc[mt][2 * nt2][3],
                            af[mt][0], af[mt][1], af[mt][2], af[mt][3], b0, b1);
                    mma_f16(acc[mt][2 * nt2 + 1][0], acc[mt][2 * nt2 + 1][1],
                            acc[mt][2 * nt2 + 1][2], acc[mt][2 * nt2 + 1][3],
                            af[mt][0], af[mt][1], af[mt][2], af[mt][3], b2, b3);
                }
            }
        }
    }

    if (mode == 1 || mode == 3) {
        __syncthreads();
#pragma unroll
        for (int mt = 0; mt < 2; mt++) {
#pragma unroll
            for (int half = 0; half < 2; half++) {
                float s = 0.f, ss = 0.f;
#pragma unroll
                for (int nt = 0; nt < 4; nt++) {
                    float v0 = acc[mt][nt][2 * half];
                    float v1 = acc[mt][nt][2 * half + 1];
                    s += v0 + v1;
                    ss += v0 * v0 + v1 * v1;
                }
                s += __shfl_xor_sync(0xffffffffu, s, 1);
                s += __shfl_xor_sync(0xffffffffu, s, 2);
                ss += __shfl_xor_sync(0xffffffffu, ss, 1);
                ss += __shfl_xor_sync(0xffffffffu, ss, 2);
                if (q4 == 0) {
                    int row = wm + mt * 16 + half * 8 + r4;
                    red[(wn * 128 + row) * 2 + 0] = s;
                    red[(wn * 128 + row) * 2 + 1] = ss;
                }
            }
        }
        __syncthreads();
#pragma unroll
        for (int mt = 0; mt < 2; mt++) {
#pragma unroll
            for (int half = 0; half < 2; half++) {
                int row = wm + mt * 16 + half * 8 + r4;
                float S  = red[row * 2 + 0] + red[(128 + row) * 2 + 0];
                float SS = red[row * 2 + 1] + red[(128 + row) * 2 + 1];
                float m = S * (1.f / 64.f);
                float var = SS * (1.f / 64.f) - m * m;
                float rr = rsqrtf(var + EPSLN);
#pragma unroll
                for (int nt = 0; nt < 4; nt++) {
                    int ci = wncol + nt * 8 + 2 * q4;
                    float o0 = ((acc[mt][nt][2 * half]     - m) * rr * lng[ci]     + lnb[ci])     * lscale;
                    float o1 = ((acc[mt][nt][2 * half + 1] - m) * rr * lng[ci + 1] + lnb[ci + 1]) * lscale;
                    __half* cp = Ch + (size_t)(bm + row) * DIMSZ + bn + ci;
                    *(__half2*)cp = __floats2half2_rn(o0, o1);
                }
            }
        }
    } else if (mode == 2) {
#pragma unroll
        for (int mt = 0; mt < 2; mt++) {
            int r0 = bm + wm + mt * 16 + r4;
#pragma unroll
            for (int nt = 0; nt < 4; nt++) {
                __half* cp = Ch + (size_t)r0 * DIMSZ + bn + wncol + nt * 8 + 2 * q4;
                *(__half2*)cp = __floats2half2_rn(acc[mt][nt][0], acc[mt][nt][1]);
                *(__half2*)(cp + (size_t)8 * DIMSZ) =
                    __floats2half2_rn(acc[mt][nt][2], acc[mt][nt][3]);
            }
        }
    } else {
#pragma unroll
        for (int mt = 0; mt < 2; mt++) {
            int r0 = bm + wm + mt * 16 + r4;
#pragma unroll
            for (int nt = 0; nt < 4; nt++) {
                float* cp = C + (size_t)r0 * DIMSZ + bn + wncol + nt * 8 + 2 * q4;
                *(float2*)cp = make_float2(acc[mt][nt][0], acc[mt][nt][1]);
                *(float2*)(cp + (size_t)8 * DIMSZ) =
                    make_float2(acc[mt][nt][2], acc[mt][nt][3]);
            }
        }
    }
}

__global__ __launch_bounds__(256, 2) void gemm_qkv(
    const __half* __restrict__ xh, const __half* __restrict__ wh,
    __half* __restrict__ Qh, __half* __restrict__ Kp, __half* __restrict__ Vp,
    const float* __restrict__ qg, const float* __restrict__ qb,
    const float* __restrict__ kg, const float* __restrict__ kb)
{
    const int z = blockIdx.z;
    const __half* A  = xh + (size_t)z * BSROWS * DIMSZ;
    const __half* Bw = wh + (size_t)z * DIMSZ * DIMSZ;
    __half* Ch      = (z == 0) ? Qh : (z == 1) ? Kp : Vp;
    const float* g  = (z == 0) ? qg : kg;
    const float* bb = (z == 0) ? qb : kb;
    float sc        = (z == 0) ? 0.125f : 1.0f;
    int mode        = (z == 0) ? 1 : (z == 1) ? 3 : 2;
    gemm_body(A, Bw, nullptr, Ch, blockIdx.y * 128, blockIdx.x * 64, mode, g, bb, sc);
}

__global__ __launch_bounds__(256, 2) void gemm_proj(
    const __half* __restrict__ A, const __half* __restrict__ Bw, float* __restrict__ C)
{
    gemm_body(A, Bw, C, nullptr, blockIdx.y * 128, blockIdx.x * 64, 0, nullptr, nullptr, 1.f);
}

// ---------------------------------------------------------------------------
// Full-row layernorm over D=512: fp32 in, fp16 out. One warp per row.
// ---------------------------------------------------------------------------
__global__ __launch_bounds__(256) void ln_full(
    const float* __restrict__ X, __half* __restrict__ Xh,
    const float* __restrict__ g, const float* __restrict__ bb)
{
    int row = blockIdx.x * 8 + (threadIdx.x >> 5);
    int lane = threadIdx.x & 31;
    const float* p = X + (size_t)row * DIMSZ;
    float4 x[4];
    float s = 0.f;
#pragma unroll
    for (int q = 0; q < 4; q++) {
        x[q] = *(const float4*)(p + lane * 4 + q * 128);
        s += x[q].x + x[q].y + x[q].z + x[q].w;
    }
#pragma unroll
    for (int off = 16; off; off >>= 1) s += __shfl_xor_sync(0xffffffffu, s, off);
    float m = s * (1.f / 512.f);
    float v = 0.f;
#pragma unroll
    for (int q = 0; q < 4; q++) {
        x[q].x -= m; x[q].y -= m; x[q].z -= m; x[q].w -= m;
        v += x[q].x * x[q].x + x[q].y * x[q].y + x[q].z * x[q].z + x[q].w * x[q].w;
    }
#pragma unroll
    for (int off = 16; off; off >>= 1) v += __shfl_xor_sync(0xffffffffu, v, off);
    float r = rsqrtf(v * (1.f / 512.f) + EPSLN);
#pragma unroll
    for (int q = 0; q < 4; q++) {
        int c = lane * 4 + q * 128;
        float4 gg = *(const float4*)(g + c);
        float4 bv = *(const float4*)(bb + c);
        uint2 st = make_uint2(
            f16x2_of(x[q].x * r * gg.x + bv.x, x[q].y * r * gg.y + bv.y),
            f16x2_of(x[q].z * r * gg.z + bv.z, x[q].w * r * gg.w + bv.w));
        *(uint2*)(Xh + (size_t)row * DIMSZ + c) = st;
    }
}

// ---------------------------------------------------------------------------
// Fused flash attention: fp16, fixed-max softmax, TMA double-buffered K/V.
// K/V stage = 128 keys x 64 halves, packed 128B rows, SW128 swizzle.
// Swizzle reduces to addr ^= (key&7)<<4; key&7 == ldmatrix lane_r for both
// the K (non-trans) and V (trans) fragment maps -> one XOR per ldsm.
// One TMA 2D load per tensor per stage replaces 1024 cp.async LSU ops.
// ---------------------------------------------------------------------------
#define KVSB 16384u                      // bytes per stage per tensor
#define ATTN_SMEM (4 * 16384 + 16)       // K0 K1 V0 V1 + 2 mbarriers
#define MBAR_OFF  (4 * 16384)
#define NSTG (NB / 128)                  // 32 stages
#define PEXPC 7.2134752f                 // 5.0 * log2(e)

__global__ __launch_bounds__(256, 2) void attn_mma(
    const __grid_constant__ CUtensorMap km,
    const __grid_constant__ CUtensorMap vm,
    const __half* __restrict__ Qh, float* __restrict__ Xo)
{
    extern __shared__ __half asm_h[];    // [K0][K1][V0][V1][mbar0 mbar1]
    const uint32_t sm_u = (uint32_t)__cvta_generic_to_shared(asm_h);

    const int bh = blockIdx.x;
    const int b = bh >> 3, h = bh & 7;
    const int tid = threadIdx.x;
    const int w = tid >> 5, lane = tid & 31;
    const int q4 = lane & 3, r4 = lane >> 2;

    const int lm_mat = lane >> 3, lm_r = lane & 7;
    const uint32_t lxor = (uint32_t)(lm_r << 4);
    // lane bases within a 64-key block (bytes), pre-swizzle
    const uint32_t klm_off =
        (uint32_t)(((lm_mat >> 1) * 8 + lm_r) * 128 + (lm_mat & 1) * 16);
    const uint32_t vlm_off =
        (uint32_t)(((lm_mat & 1) * 8 + lm_r) * 128 + (lm_mat >> 1) * 16);

    // init mbarriers + issue stage 0
    if (tid == 0) {
        mbar_init(sm_u + MBAR_OFF, 1);
        mbar_init(sm_u + MBAR_OFF + 8, 1);
    }
    __syncthreads();
    if (tid == 0) {
        mbar_expect(sm_u + MBAR_OFF, 2 * KVSB);
        tma2d(sm_u, &km, h * HDIM, 0, sm_u + MBAR_OFF);
        tma2d(sm_u + 2 * KVSB, &vm, h * HDIM, 0, sm_u + MBAR_OFF);
    }

    // Q fragments: fp16 in gmem, adjacent pairs -> direct 32-bit loads
    unsigned qa[4][4];
    {
        const __half* q0 = Qh + (size_t)(b * SQ + w * 16 + r4) * DIMSZ + h * HDIM;
        const __half* q1 = q0 + 8 * DIMSZ;
#pragma unroll
        for (int kk = 0; kk < 4; kk++) {
            int col = kk * 16 + 2 * q4;
            qa[kk][0] = *(const unsigned*)(q0 + col);
            qa[kk][1] = *(const unsigned*)(q1 + col);
            qa[kk][2] = *(const unsigned*)(q0 + col + 8);
            qa[kk][3] = *(const unsigned*)(q1 + col + 8);
        }
    }

    float lA = 0.f, lB = 0.f;
    float o[8][4];
#pragma unroll
    for (int dt = 0; dt < 8; dt++)
        o[dt][0] = o[dt][1] = o[dt][2] = o[dt][3] = 0.f;

    unsigned ph0 = 0, ph1 = 0;
    for (int t = 0; t < NSTG; t++) {
        int st = t & 1;
        // wait current stage full
        if (st == 0) { mbar_wait(sm_u + MBAR_OFF, ph0); ph0 ^= 1; }
        else         { mbar_wait(sm_u + MBAR_OFF + 8, ph1); ph1 ^= 1; }
        __syncthreads();          // all warps past wait => compute(t-1) done
        if (t + 1 < NSTG && tid == 0) {
            int ns = st ^ 1;
            uint32_t mb = sm_u + MBAR_OFF + ns * 8;
            mbar_expect(mb, 2 * KVSB);
            tma2d(sm_u + ns * KVSB, &km, h * HDIM, (t + 1) * 128, mb);
            tma2d(sm_u + 2 * KVSB + ns * KVSB, &vm, h * HDIM, (t + 1) * 128, mb);
        }

#pragma unroll
        for (int sub = 0; sub < 2; sub++) {
            const uint32_t kbb = sm_u + (uint32_t)st * KVSB + (uint32_t)(sub * 8192) + klm_off;
            const uint32_t vbb = sm_u + 2 * KVSB + (uint32_t)st * KVSB + (uint32_t)(sub * 8192) + vlm_off;

            // ---- scores: S = Q K^T ----
            float s[8][4];
#pragma unroll
            for (int nt = 0; nt < 8; nt++)
                s[nt][0] = s[nt][1] = s[nt][2] = s[nt][3] = 0.f;
#pragma unroll
            for (int kk = 0; kk < 4; kk++) {
#pragma unroll
                for (int nt2 = 0; nt2 < 4; nt2++) {
                    unsigned b0, b1, b2, b3;
                    ldsm4(b0, b1, b2, b3,
                          (kbb + (uint32_t)(nt2 * 2048 + kk * 32)) ^ lxor);
                    mma_f16(s[2 * nt2][0], s[2 * nt2][1], s[2 * nt2][2], s[2 * nt2][3],
                            qa[kk][0], qa[kk][1], qa[kk][2], qa[kk][3], b0, b1);
                    mma_f16(s[2 * nt2 + 1][0], s[2 * nt2 + 1][1], s[2 * nt2 + 1][2], s[2 * nt2 + 1][3],
                            qa[kk][0], qa[kk][1], qa[kk][2], qa[kk][3], b2, b3);
                }
            }

            // ---- fixed-max softmax; pack P into fp16 A-fragments ----
            float suA = 0.f, suB = 0.f;
            unsigned ph[4][4];
#pragma unroll
            for (int nt = 0; nt < 8; nt++) {
                float p0 = exp2f(fmaf(s[nt][0], 1.44269504f, -PEXPC));
                float p1 = exp2f(fmaf(s[nt][1], 1.44269504f, -PEXPC));
                float p2 = exp2f(fmaf(s[nt][2], 1.44269504f, -PEXPC));
                float p3 = exp2f(fmaf(s[nt][3], 1.44269504f, -PEXPC));
                suA += p0 + p1; suB += p2 + p3;
                int tt = nt >> 1;
                if ((nt & 1) == 0) {
                    ph[tt][0] = f16x2_of(p0, p1);
                    ph[tt][1] = f16x2_of(p2, p3);
                } else {
                    ph[tt][2] = f16x2_of(p0, p1);
                    ph[tt][3] = f16x2_of(p2, p3);
                }
            }
            lA += suA;
            lB += suB;

            // ---- O += P @ V ----
#pragma unroll
            for (int kk = 0; kk < 4; kk++) {
#pragma unroll
                for (int dt2 = 0; dt2 < 4; dt2++) {
                    unsigned v0, v1, v2, v3;
                    ldsm4t(v0, v1, v2, v3,
                           (vbb + (uint32_t)(kk * 2048 + dt2 * 32)) ^ lxor);
                    mma_f16(o[2 * dt2][0], o[2 * dt2][1], o[2 * dt2][2], o[2 * dt2][3],
                            ph[kk][0], ph[kk][1], ph[kk][2], ph[kk][3], v0, v1);
                    mma_f16(o[2 * dt2 + 1][0], o[2 * dt2 + 1][1], o[2 * dt2 + 1][2], o[2 * dt2 + 1][3],
                            ph[kk][0], ph[kk][1], ph[kk][2], ph[kk][3], v2, v3);
                }
            }
        }
    }

    lA += __shfl_xor_sync(0xffffffffu, lA, 1);
    lA += __shfl_xor_sync(0xffffffffu, lA, 2);
    lB += __shfl_xor_sync(0xffffffffu, lB, 1);
    lB += __shfl_xor_sync(0xffffffffu, lB, 2);
    float ivA = 1.f / lA, ivB = 1.f / lB;
    int rowA = b * SQ + w * 16 + r4;
    float* xoA = Xo + (size_t)rowA * DIMSZ + h * HDIM + 2 * q4;
    float* xoB = xoA + 8 * DIMSZ;
#pragma unroll
    for (int dt = 0; dt < 8; dt++) {
        *(float2*)(xoA + dt * 8) = make_float2(o[dt][0] * ivA, o[dt][1] * ivA);
        *(float2*)(xoB + dt * 8) = make_float2(o[dt][2] * ivB, o[dt][3] * ivB);
    }
}

// ---------------------------------------------------------------------------
// host: tensor-map encode via runtime-resolved driver entry point
// ---------------------------------------------------------------------------
typedef CUresult (*tmap_enc_fn)(
    CUtensorMap*, CUtensorMapDataType, cuuint32_t, void*,
    const cuuint64_t*, const cuuint64_t*, const cuuint32_t*, const cuuint32_t*,
    CUtensorMapInterleave, CUtensorMapSwizzle, CUtensorMapL2promotion,
    CUtensorMapFloatOOBfill);

static tmap_enc_fn get_enc() {
    static tmap_enc_fn fn = nullptr;
    if (!fn) {
        void* p = nullptr;
        cudaDriverEntryPointQueryResult st;
#if CUDART_VERSION >= 12050
        cudaGetDriverEntryPointByVersion("cuTensorMapEncodeTiled", &p, 12000,
                                         cudaEnableDefault, &st);
#else
        cudaGetDriverEntryPoint("cuTensorMapEncodeTiled", &p,
                                cudaEnableDefault, &st);
#endif
        fn = (tmap_enc_fn)p;
    }
    return fn;
}

static void encode_kv_map(CUtensorMap* m, void* base) {
    cuuint64_t gdim[2] = { DIMSZ, NB };          // inner elems, rows
    cuuint64_t gstr[1] = { DIMSZ * 2 };          // row stride bytes
    cuuint32_t box[2]  = { HDIM, 128 };          // 64 elems x 128 keys
    cuuint32_t estr[2] = { 1, 1 };
    get_enc()(m, CU_TENSOR_MAP_DATA_TYPE_FLOAT16, 2, base,
              gdim, gstr, box, estr,
              CU_TENSOR_MAP_INTERLEAVE_NONE, CU_TENSOR_MAP_SWIZZLE_128B,
              CU_TENSOR_MAP_L2_PROMOTION_L2_128B,
              CU_TENSOR_MAP_FLOAT_OOB_FILL_NONE);
}

// ---------------------------------------------------------------------------
extern "C" void kernel_launch(void* const* d_in, const int* in_sizes, int n_in,
                              void* d_out, int out_size)
{
    const float* x_q   = (const float*)d_in[0];
    const float* x_k   = (const float*)d_in[1];
    const float* x_v   = (const float*)d_in[2];
    const float* Wq    = (const float*)d_in[3];
    const float* Wk    = (const float*)d_in[4];
    const float* Wv    = (const float*)d_in[5];
    const float* Wproj = (const float*)d_in[6];
    const float* qn_g  = (const float*)d_in[7];
    const float* qn_b  = (const float*)d_in[8];
    const float* kn_g  = (const float*)d_in[9];
    const float* kn_b  = (const float*)d_in[10];
    const float* n_g   = (const float*)d_in[11];
    const float* n_b   = (const float*)d_in[12];
    float* out = (float*)d_out;

    float *Xp;
    __half *Qh, *Kp, *Vp, *xh, *wh, *Xh;
    cudaGetSymbolAddress((void**)&Qh, g_Qh);
    cudaGetSymbolAddress((void**)&Kp, g_K);
    cudaGetSymbolAddress((void**)&Vp, g_V);
    cudaGetSymbolAddress((void**)&Xp, g_X);
    cudaGetSymbolAddress((void**)&xh, g_xh);
    cudaGetSymbolAddress((void**)&wh, g_wh);
    cudaGetSymbolAddress((void**)&Xh, g_Xh);

    static bool attr_set = false;
    if (!attr_set) {
        cudaFuncSetAttribute(gemm_qkv,
                             cudaFuncAttributeMaxDynamicSharedMemorySize, GEMM_SMEM);
        cudaFuncSetAttribute(gemm_proj,
                             cudaFuncAttributeMaxDynamicSharedMemorySize, GEMM_SMEM);
        cudaFuncSetAttribute(attn_mma,
                             cudaFuncAttributeMaxDynamicSharedMemorySize, ATTN_SMEM);
        attr_set = true;
    }

    // tensor maps for K/V (pure host compute; passed by value -> capture-safe)
    CUtensorMap kmap, vmap;
    encode_kv_map(&kmap, Kp);
    encode_kv_map(&vmap, Vp);

    // fp32 -> fp16 inputs (x_q/x_k/x_v + 4 weights)
    dim3 cvt_grid(BSROWS * DIMSZ / (256 * 8), 7);
    cvt_f2h<<<cvt_grid, 256>>>(x_q, x_k, x_v, Wq, Wk, Wv, Wproj, xh, wh);

    // fused Q/K/V projections + per-head LN (fp16 out) / V fp16 (3-stage pipe)
    dim3 qkv_grid(DIMSZ / 64, BSROWS / 128, 3);
    gemm_qkv<<<qkv_grid, 256, GEMM_SMEM>>>(xh, wh, Qh, Kp, Vp,
                                           qn_g, qn_b, kn_g, kn_b);

    // fused attention (TMA-fed K/V pipeline)
    attn_mma<<<BSZ * NHEAD, 256, ATTN_SMEM>>>(kmap, vmap, Qh, Xp);

    // output layernorm (fp16 out) + projection
    ln_full<<<BSROWS / 8, 256>>>(Xp, Xh, n_g, n_b);
    dim3 proj_grid(DIMSZ / 64, BSROWS / 128);
    gemm_proj<<<proj_grid, 256, GEMM_SMEM>>>(Xh, wh + 3 * DIMSZ * DIMSZ, out);
}

// round 17
// speedup vs baseline: 2.3671x; 1.0403x over previous
#include <cuda_runtime.h>
#include <cuda.h>
#include <cuda_fp16.h>
#include <cstdint>

#define DIMSZ 512
#define NHEAD 8
#define HDIM  64
#define NB    4096
#define BSZ   32
#define SQ    128
#define BSROWS 4096
#define EPSLN 1e-5f

// scratch (allocation-free rule: __device__ globals)
__device__ __half g_xh[3 * BSROWS * DIMSZ];   // x_q, x_k, x_v in fp16
__device__ __half g_wh[4 * DIMSZ * DIMSZ];    // Wq, Wk, Wv, Wproj in fp16
__device__ __half g_Qh[BSROWS * DIMSZ];
__device__ __half g_K[NB * DIMSZ];
__device__ __half g_V[NB * DIMSZ];
__device__ float  g_X[BSROWS * DIMSZ];
__device__ __half g_Xh[BSROWS * DIMSZ];

// ---------------------------------------------------------------------------
// helpers
// ---------------------------------------------------------------------------
__device__ __forceinline__ void mma_f16(
    float& c0, float& c1, float& c2, float& c3,
    unsigned a0, unsigned a1, unsigned a2, unsigned a3,
    unsigned b0, unsigned b1)
{
    asm volatile(
        "mma.sync.aligned.m16n8k16.row.col.f32.f16.f16.f32 "
        "{%0,%1,%2,%3}, {%4,%5,%6,%7}, {%8,%9}, {%0,%1,%2,%3};"
        : "+f"(c0), "+f"(c1), "+f"(c2), "+f"(c3)
        : "r"(a0), "r"(a1), "r"(a2), "r"(a3), "r"(b0), "r"(b1));
}
__device__ __forceinline__ unsigned f16x2_of(float lo, float hi) {
    unsigned d;
    asm("cvt.rn.f16x2.f32 %0, %1, %2;" : "=r"(d) : "f"(hi), "f"(lo));
    return d;
}
__device__ __forceinline__ void ldsm4(
    unsigned& r0, unsigned& r1, unsigned& r2, unsigned& r3, uint32_t addr)
{
    asm volatile(
        "ldmatrix.sync.aligned.m8n8.x4.shared.b16 {%0,%1,%2,%3}, [%4];"
        : "=r"(r0), "=r"(r1), "=r"(r2), "=r"(r3) : "r"(addr));
}
__device__ __forceinline__ void ldsm4t(
    unsigned& r0, unsigned& r1, unsigned& r2, unsigned& r3, uint32_t addr)
{
    asm volatile(
        "ldmatrix.sync.aligned.m8n8.x4.trans.shared.b16 {%0,%1,%2,%3}, [%4];"
        : "=r"(r0), "=r"(r1), "=r"(r2), "=r"(r3) : "r"(addr));
}
// mbarrier / TMA helpers
__device__ __forceinline__ void mbar_init(uint32_t a, uint32_t cnt) {
    asm volatile("mbarrier.init.shared.b64 [%0], %1;" :: "r"(a), "r"(cnt) : "memory");
}
__device__ __forceinline__ void mbar_expect(uint32_t a, uint32_t bytes) {
    asm volatile("mbarrier.arrive.expect_tx.shared.b64 _, [%0], %1;"
                 :: "r"(a), "r"(bytes) : "memory");
}
__device__ __forceinline__ void mbar_wait(uint32_t a, uint32_t ph) {
    asm volatile(
        "{\n\t.reg .pred P;\n"
        "LW%=:\n\t"
        "mbarrier.try_wait.parity.acquire.cta.shared::cta.b64 P, [%0], %1;\n\t"
        "@P bra.uni LD%=;\n\t"
        "bra.uni LW%=;\n"
        "LD%=:\n\t}"
        :: "r"(a), "r"(ph) : "memory");
}
__device__ __forceinline__ void tma2d(
    uint32_t saddr, const void* map, int cx, int cy, uint32_t mbar)
{
    asm volatile(
        "cp.async.bulk.tensor.2d.shared::cta.global.tile.mbarrier::complete_tx::bytes "
        "[%0], [%1, {%2, %3}], [%4];"
        :: "r"(saddr), "l"(map), "r"(cx), "r"(cy), "r"(mbar) : "memory");
}

// ---------------------------------------------------------------------------
// fp32 -> fp16 conversion pass for x_q/x_k/x_v (z=0..2) and W's (z=3..6)
// ---------------------------------------------------------------------------
__global__ __launch_bounds__(256) void cvt_f2h(
    const float* __restrict__ x_q, const float* __restrict__ x_k,
    const float* __restrict__ x_v,
    const float* __restrict__ Wq, const float* __restrict__ Wk,
    const float* __restrict__ Wv, const float* __restrict__ Wp,
    __half* __restrict__ xh, __half* __restrict__ wh)
{
    int z = blockIdx.y;
    const float* s;
    __half* d;
    int n;
    if (z < 3) {
        s = (z == 0) ? x_q : (z == 1) ? x_k : x_v;
        d = xh + (size_t)z * BSROWS * DIMSZ;
        n = BSROWS * DIMSZ;
    } else {
        int zz = z - 3;
        s = (zz == 0) ? Wq : (zz == 1) ? Wk : (zz == 2) ? Wv : Wp;
        d = wh + (size_t)zz * DIMSZ * DIMSZ;
        n = DIMSZ * DIMSZ;
    }
    int idx = (blockIdx.x * 256 + threadIdx.x) * 8;
    if (idx >= n) return;
    float4 a = *(const float4*)(s + idx);
    float4 b = *(const float4*)(s + idx + 4);
    *(uint4*)(d + idx) = make_uint4(
        f16x2_of(a.x, a.y), f16x2_of(a.z, a.w),
        f16x2_of(b.x, b.y), f16x2_of(b.z, b.w));
}

// ---------------------------------------------------------------------------
// fp16 GEMM (fp32 accumulate), TMA double-buffered, single barrier per k-tile.
// smem tiles: packed 128-B rows, SW128 swizzle (addr ^= (row&7)<<4 = lane_r<<4).
// Per k-tile: 2 TMA loads (A 128x64, B 64x64) replace 1536 LSU cp.asyncs.
// Epilogue modes: 0 plain fp32, 1/3 per-head LN -> fp16 (Q/K), 2 fp16 (V).
// ---------------------------------------------------------------------------
#define GA_B 16384u                 // A stage bytes (128 rows x 128 B)
#define GB_B 8192u                  // B stage bytes (64 rows x 128 B)
#define GB_OFF (2 * GA_B)           // B region base
#define GMB_OFF (2 * GA_B + 2 * GB_B)
#define GEMM_SMEM (2 * 16384 + 2 * 8192 + 16)
#define NKT  (DIMSZ / 64)           // 8 k-tiles

__device__ __forceinline__ void gemm_body(
    const CUtensorMap* am, const CUtensorMap* bmp,
    int arow0, int brow0,
    float* __restrict__ C, __half* __restrict__ Ch,
    int bm, int bn, int mode,
    const float* __restrict__ lng, const float* __restrict__ lnb, float lscale)
{
    extern __shared__ __half gsmh[];   // [A0][A1][B0][B1][mbar0 mbar1]
    float* red = (float*)gsmh;         // LN reduce buffer aliases A0 in epilogue
    const uint32_t sm_u = (uint32_t)__cvta_generic_to_shared(gsmh);

    const int tid = threadIdx.x;
    const int lane = tid & 31, w = tid >> 5;
    const int q4 = lane & 3, r4 = lane >> 2;
    const int wm = (w & 3) * 32;
    const int wn = (w >> 2);
    const int wncol = wn * 32;

    const int lm_mat = lane >> 3, lm_r = lane & 7;
    const uint32_t lxor = (uint32_t)(lm_r << 4);
    // A (non-trans): row = wm + mt*16 + (mat&1)*8 + lm_r, col = kk*16 + (mat>>1)*8
    const uint32_t alm_off =
        (uint32_t)((wm + (lm_mat & 1) * 8 + lm_r) * 128 + (lm_mat >> 1) * 16);
    // B (non-trans): row = wncol + nt2*16 + (mat>>1)*8 + lm_r, col = kk*16 + (mat&1)*8
    const uint32_t blm_off = GB_OFF +
        (uint32_t)((wncol + (lm_mat >> 1) * 8 + lm_r) * 128 + (lm_mat & 1) * 16);

    // init mbarriers + issue stage 0
    if (tid == 0) {
        mbar_init(sm_u + GMB_OFF, 1);
        mbar_init(sm_u + GMB_OFF + 8, 1);
    }
    __syncthreads();
    if (tid == 0) {
        mbar_expect(sm_u + GMB_OFF, GA_B + GB_B);
        tma2d(sm_u, am, 0, arow0, sm_u + GMB_OFF);
        tma2d(sm_u + GB_OFF, bmp, 0, brow0, sm_u + GMB_OFF);
    }

    float acc[2][4][4];
#pragma unroll
    for (int mt = 0; mt < 2; mt++)
#pragma unroll
        for (int nt = 0; nt < 4; nt++)
#pragma unroll
            for (int c = 0; c < 4; c++) acc[mt][nt][c] = 0.f;

    unsigned ph0 = 0, ph1 = 0;
    for (int t = 0; t < NKT; t++) {
        int st = t & 1;
        if (st == 0) { mbar_wait(sm_u + GMB_OFF, ph0); ph0 ^= 1; }
        else         { mbar_wait(sm_u + GMB_OFF + 8, ph1); ph1 ^= 1; }
        __syncthreads();          // all warps past wait => compute(t-1) done
        if (t + 1 < NKT && tid == 0) {
            int ns = st ^ 1;
            uint32_t mb = sm_u + GMB_OFF + ns * 8;
            mbar_expect(mb, GA_B + GB_B);
            tma2d(sm_u + ns * GA_B, am, (t + 1) * 64, arow0, mb);
            tma2d(sm_u + GB_OFF + ns * GB_B, bmp, (t + 1) * 64, brow0, mb);
        }

        const uint32_t abase = sm_u + (uint32_t)st * GA_B + alm_off;
        const uint32_t bbase = sm_u + (uint32_t)st * GB_B + blm_off;
#pragma unroll
        for (int kk = 0; kk < 4; kk++) {
            unsigned af[2][4];
#pragma unroll
            for (int mt = 0; mt < 2; mt++)
                ldsm4(af[mt][0], af[mt][1], af[mt][2], af[mt][3],
                      (abase + (uint32_t)(mt * 2048 + kk * 32)) ^ lxor);
#pragma unroll
            for (int nt2 = 0; nt2 < 2; nt2++) {
                unsigned b0, b1, b2, b3;
                ldsm4(b0, b1, b2, b3,
                      (bbase + (uint32_t)(nt2 * 2048 + kk * 32)) ^ lxor);
#pragma unroll
                for (int mt = 0; mt < 2; mt++) {
                    mma_f16(acc[mt][2 * nt2][0], acc[mt][2 * nt2][1],
                            acc[mt][2 * nt2][2], acc[mt][2 * nt2][3],
                            af[mt][0], af[mt][1], af[mt][2], af[mt][3], b0, b1);
                    mma_f16(acc[mt][2 * nt2 + 1][0], acc[mt][2 * nt2 + 1][1],
                            acc[mt][2 * nt2 + 1][2], acc[mt][2 * nt2 + 1][3],
                            af[mt][0], af[mt][1], af[mt][2], af[mt][3], b2, b3);
                }
            }
        }
    }

    if (mode == 1 || mode == 3) {
        // -------- fused per-head layernorm (fp16 out) --------
        __syncthreads();
#pragma unroll
        for (int mt = 0; mt < 2; mt++) {
#pragma unroll
            for (int half = 0; half < 2; half++) {
                float s = 0.f, ss = 0.f;
#pragma unroll
                for (int nt = 0; nt < 4; nt++) {
                    float v0 = acc[mt][nt][2 * half];
                    float v1 = acc[mt][nt][2 * half + 1];
                    s += v0 + v1;
                    ss += v0 * v0 + v1 * v1;
                }
                s += __shfl_xor_sync(0xffffffffu, s, 1);
                s += __shfl_xor_sync(0xffffffffu, s, 2);
                ss += __shfl_xor_sync(0xffffffffu, ss, 1);
                ss += __shfl_xor_sync(0xffffffffu, ss, 2);
                if (q4 == 0) {
                    int row = wm + mt * 16 + half * 8 + r4;
                    red[(wn * 128 + row) * 2 + 0] = s;
                    red[(wn * 128 + row) * 2 + 1] = ss;
                }
            }
        }
        __syncthreads();
#pragma unroll
        for (int mt = 0; mt < 2; mt++) {
#pragma unroll
            for (int half = 0; half < 2; half++) {
                int row = wm + mt * 16 + half * 8 + r4;
                float S  = red[row * 2 + 0] + red[(128 + row) * 2 + 0];
                float SS = red[row * 2 + 1] + red[(128 + row) * 2 + 1];
                float m = S * (1.f / 64.f);
                float var = SS * (1.f / 64.f) - m * m;
                float rr = rsqrtf(var + EPSLN);
#pragma unroll
                for (int nt = 0; nt < 4; nt++) {
                    int ci = wncol + nt * 8 + 2 * q4;
                    float o0 = ((acc[mt][nt][2 * half]     - m) * rr * lng[ci]     + lnb[ci])     * lscale;
                    float o1 = ((acc[mt][nt][2 * half + 1] - m) * rr * lng[ci + 1] + lnb[ci + 1]) * lscale;
                    __half* cp = Ch + (size_t)(bm + row) * DIMSZ + bn + ci;
                    *(__half2*)cp = __floats2half2_rn(o0, o1);
                }
            }
        }
    } else if (mode == 2) {
#pragma unroll
        for (int mt = 0; mt < 2; mt++) {
            int r0 = bm + wm + mt * 16 + r4;
#pragma unroll
            for (int nt = 0; nt < 4; nt++) {
                __half* cp = Ch + (size_t)r0 * DIMSZ + bn + wncol + nt * 8 + 2 * q4;
                *(__half2*)cp = __floats2half2_rn(acc[mt][nt][0], acc[mt][nt][1]);
                *(__half2*)(cp + (size_t)8 * DIMSZ) =
                    __floats2half2_rn(acc[mt][nt][2], acc[mt][nt][3]);
            }
        }
    } else {
#pragma unroll
        for (int mt = 0; mt < 2; mt++) {
            int r0 = bm + wm + mt * 16 + r4;
#pragma unroll
            for (int nt = 0; nt < 4; nt++) {
                float* cp = C + (size_t)r0 * DIMSZ + bn + wncol + nt * 8 + 2 * q4;
                *(float2*)cp = make_float2(acc[mt][nt][0], acc[mt][nt][1]);
                *(float2*)(cp + (size_t)8 * DIMSZ) =
                    make_float2(acc[mt][nt][2], acc[mt][nt][3]);
            }
        }
    }
}

__global__ __launch_bounds__(256, 2) void gemm_qkv(
    const __grid_constant__ CUtensorMap xm,
    const __grid_constant__ CUtensorMap wm_,
    __half* __restrict__ Qh, __half* __restrict__ Kp, __half* __restrict__ Vp,
    const float* __restrict__ qg, const float* __restrict__ qb,
    const float* __restrict__ kg, const float* __restrict__ kb)
{
    const int z = blockIdx.z;
    __half* Ch      = (z == 0) ? Qh : (z == 1) ? Kp : Vp;
    const float* g  = (z == 0) ? qg : kg;
    const float* bb = (z == 0) ? qb : kb;
    float sc        = (z == 0) ? 0.125f : 1.0f;
    int mode        = (z == 0) ? 1 : (z == 1) ? 3 : 2;
    int bm = blockIdx.y * 128, bn = blockIdx.x * 64;
    gemm_body(&xm, &wm_, z * BSROWS + bm, z * DIMSZ + bn,
              nullptr, Ch, bm, bn, mode, g, bb, sc);
}

__global__ __launch_bounds__(256, 2) void gemm_proj(
    const __grid_constant__ CUtensorMap xm,
    const __grid_constant__ CUtensorMap wm_,
    float* __restrict__ C)
{
    int bm = blockIdx.y * 128, bn = blockIdx.x * 64;
    gemm_body(&xm, &wm_, bm, 3 * DIMSZ + bn,
              C, nullptr, bm, bn, 0, nullptr, nullptr, 1.f);
}

// ---------------------------------------------------------------------------
// Full-row layernorm over D=512: fp32 in, fp16 out. One warp per row.
// ---------------------------------------------------------------------------
__global__ __launch_bounds__(256) void ln_full(
    const float* __restrict__ X, __half* __restrict__ Xh,
    const float* __restrict__ g, const float* __restrict__ bb)
{
    int row = blockIdx.x * 8 + (threadIdx.x >> 5);
    int lane = threadIdx.x & 31;
    const float* p = X + (size_t)row * DIMSZ;
    float4 x[4];
    float s = 0.f;
#pragma unroll
    for (int q = 0; q < 4; q++) {
        x[q] = *(const float4*)(p + lane * 4 + q * 128);
        s += x[q].x + x[q].y + x[q].z + x[q].w;
    }
#pragma unroll
    for (int off = 16; off; off >>= 1) s += __shfl_xor_sync(0xffffffffu, s, off);
    float m = s * (1.f / 512.f);
    float v = 0.f;
#pragma unroll
    for (int q = 0; q < 4; q++) {
        x[q].x -= m; x[q].y -= m; x[q].z -= m; x[q].w -= m;
        v += x[q].x * x[q].x + x[q].y * x[q].y + x[q].z * x[q].z + x[q].w * x[q].w;
    }
#pragma unroll
    for (int off = 16; off; off >>= 1) v += __shfl_xor_sync(0xffffffffu, v, off);
    float r = rsqrtf(v * (1.f / 512.f) + EPSLN);
#pragma unroll
    for (int q = 0; q < 4; q++) {
        int c = lane * 4 + q * 128;
        float4 gg = *(const float4*)(g + c);
        float4 bv = *(const float4*)(bb + c);
        uint2 st = make_uint2(
            f16x2_of(x[q].x * r * gg.x + bv.x, x[q].y * r * gg.y + bv.y),
            f16x2_of(x[q].z * r * gg.z + bv.z, x[q].w * r * gg.w + bv.w));
        *(uint2*)(Xh + (size_t)row * DIMSZ + c) = st;
    }
}

// ---------------------------------------------------------------------------
// Fused flash attention: fp16, fixed-max softmax, TMA double-buffered K/V.
// (unchanged from R16)
// ---------------------------------------------------------------------------
#define KVSB 16384u
#define ATTN_SMEM (4 * 16384 + 16)
#define MBAR_OFF  (4 * 16384)
#define NSTG (NB / 128)
#define PEXPC 7.2134752f

__global__ __launch_bounds__(256, 2) void attn_mma(
    const __grid_constant__ CUtensorMap km,
    const __grid_constant__ CUtensorMap vm,
    const __half* __restrict__ Qh, float* __restrict__ Xo)
{
    extern __shared__ __half asm_h[];
    const uint32_t sm_u = (uint32_t)__cvta_generic_to_shared(asm_h);

    const int bh = blockIdx.x;
    const int b = bh >> 3, h = bh & 7;
    const int tid = threadIdx.x;
    const int w = tid >> 5, lane = tid & 31;
    const int q4 = lane & 3, r4 = lane >> 2;

    const int lm_mat = lane >> 3, lm_r = lane & 7;
    const uint32_t lxor = (uint32_t)(lm_r << 4);
    const uint32_t klm_off =
        (uint32_t)(((lm_mat >> 1) * 8 + lm_r) * 128 + (lm_mat & 1) * 16);
    const uint32_t vlm_off =
        (uint32_t)(((lm_mat & 1) * 8 + lm_r) * 128 + (lm_mat >> 1) * 16);

    if (tid == 0) {
        mbar_init(sm_u + MBAR_OFF, 1);
        mbar_init(sm_u + MBAR_OFF + 8, 1);
    }
    __syncthreads();
    if (tid == 0) {
        mbar_expect(sm_u + MBAR_OFF, 2 * KVSB);
        tma2d(sm_u, &km, h * HDIM, 0, sm_u + MBAR_OFF);
        tma2d(sm_u + 2 * KVSB, &vm, h * HDIM, 0, sm_u + MBAR_OFF);
    }

    unsigned qa[4][4];
    {
        const __half* q0 = Qh + (size_t)(b * SQ + w * 16 + r4) * DIMSZ + h * HDIM;
        const __half* q1 = q0 + 8 * DIMSZ;
#pragma unroll
        for (int kk = 0; kk < 4; kk++) {
            int col = kk * 16 + 2 * q4;
            qa[kk][0] = *(const unsigned*)(q0 + col);
            qa[kk][1] = *(const unsigned*)(q1 + col);
            qa[kk][2] = *(const unsigned*)(q0 + col + 8);
            qa[kk][3] = *(const unsigned*)(q1 + col + 8);
        }
    }

    float lA = 0.f, lB = 0.f;
    float o[8][4];
#pragma unroll
    for (int dt = 0; dt < 8; dt++)
        o[dt][0] = o[dt][1] = o[dt][2] = o[dt][3] = 0.f;

    unsigned ph0 = 0, ph1 = 0;
    for (int t = 0; t < NSTG; t++) {
        int st = t & 1;
        if (st == 0) { mbar_wait(sm_u + MBAR_OFF, ph0); ph0 ^= 1; }
        else         { mbar_wait(sm_u + MBAR_OFF + 8, ph1); ph1 ^= 1; }
        __syncthreads();
        if (t + 1 < NSTG && tid == 0) {
            int ns = st ^ 1;
            uint32_t mb = sm_u + MBAR_OFF + ns * 8;
            mbar_expect(mb, 2 * KVSB);
            tma2d(sm_u + ns * KVSB, &km, h * HDIM, (t + 1) * 128, mb);
            tma2d(sm_u + 2 * KVSB + ns * KVSB, &vm, h * HDIM, (t + 1) * 128, mb);
        }

#pragma unroll
        for (int sub = 0; sub < 2; sub++) {
            const uint32_t kbb = sm_u + (uint32_t)st * KVSB + (uint32_t)(sub * 8192) + klm_off;
            const uint32_t vbb = sm_u + 2 * KVSB + (uint32_t)st * KVSB + (uint32_t)(sub * 8192) + vlm_off;

            float s[8][4];
#pragma unroll
            for (int nt = 0; nt < 8; nt++)
                s[nt][0] = s[nt][1] = s[nt][2] = s[nt][3] = 0.f;
#pragma unroll
            for (int kk = 0; kk < 4; kk++) {
#pragma unroll
                for (int nt2 = 0; nt2 < 4; nt2++) {
                    unsigned b0, b1, b2, b3;
                    ldsm4(b0, b1, b2, b3,
                          (kbb + (uint32_t)(nt2 * 2048 + kk * 32)) ^ lxor);
                    mma_f16(s[2 * nt2][0], s[2 * nt2][1], s[2 * nt2][2], s[2 * nt2][3],
                            qa[kk][0], qa[kk][1], qa[kk][2], qa[kk][3], b0, b1);
                    mma_f16(s[2 * nt2 + 1][0], s[2 * nt2 + 1][1], s[2 * nt2 + 1][2], s[2 * nt2 + 1][3],
                            qa[kk][0], qa[kk][1], qa[kk][2], qa[kk][3], b2, b3);
                }
            }

            float suA = 0.f, suB = 0.f;
            unsigned ph[4][4];
#pragma unroll
            for (int nt = 0; nt < 8; nt++) {
                float p0 = exp2f(fmaf(s[nt][0], 1.44269504f, -PEXPC));
                float p1 = exp2f(fmaf(s[nt][1], 1.44269504f, -PEXPC));
                float p2 = exp2f(fmaf(s[nt][2], 1.44269504f, -PEXPC));
                float p3 = exp2f(fmaf(s[nt][3], 1.44269504f, -PEXPC));
                suA += p0 + p1; suB += p2 + p3;
                int tt = nt >> 1;
                if ((nt & 1) == 0) {
                    ph[tt][0] = f16x2_of(p0, p1);
                    ph[tt][1] = f16x2_of(p2, p3);
                } else {
                    ph[tt][2] = f16x2_of(p0, p1);
                    ph[tt][3] = f16x2_of(p2, p3);
                }
            }
            lA += suA;
            lB += suB;

#pragma unroll
            for (int kk = 0; kk < 4; kk++) {
#pragma unroll
                for (int dt2 = 0; dt2 < 4; dt2++) {
                    unsigned v0, v1, v2, v3;
                    ldsm4t(v0, v1, v2, v3,
                           (vbb + (uint32_t)(kk * 2048 + dt2 * 32)) ^ lxor);
                    mma_f16(o[2 * dt2][0], o[2 * dt2][1], o[2 * dt2][2], o[2 * dt2][3],
                            ph[kk][0], ph[kk][1], ph[kk][2], ph[kk][3], v0, v1);
                    mma_f16(o[2 * dt2 + 1][0], o[2 * dt2 + 1][1], o[2 * dt2 + 1][2], o[2 * dt2 + 1][3],
                            ph[kk][0], ph[kk][1], ph[kk][2], ph[kk][3], v2, v3);
                }
            }
        }
    }

    lA += __shfl_xor_sync(0xffffffffu, lA, 1);
    lA += __shfl_xor_sync(0xffffffffu, lA, 2);
    lB += __shfl_xor_sync(0xffffffffu, lB, 1);
    lB += __shfl_xor_sync(0xffffffffu, lB, 2);
    float ivA = 1.f / lA, ivB = 1.f / lB;
    int rowA = b * SQ + w * 16 + r4;
    float* xoA = Xo + (size_t)rowA * DIMSZ + h * HDIM + 2 * q4;
    float* xoB = xoA + 8 * DIMSZ;
#pragma unroll
    for (int dt = 0; dt < 8; dt++) {
        *(float2*)(xoA + dt * 8) = make_float2(o[dt][0] * ivA, o[dt][1] * ivA);
        *(float2*)(xoB + dt * 8) = make_float2(o[dt][2] * ivB, o[dt][3] * ivB);
    }
}

// ---------------------------------------------------------------------------
// host: tensor-map encode via runtime-resolved driver entry point
// ---------------------------------------------------------------------------
typedef CUresult (*tmap_enc_fn)(
    CUtensorMap*, CUtensorMapDataType, cuuint32_t, void*,
    const cuuint64_t*, const cuuint64_t*, const cuuint32_t*, const cuuint32_t*,
    CUtensorMapInterleave, CUtensorMapSwizzle, CUtensorMapL2promotion,
    CUtensorMapFloatOOBfill);

static tmap_enc_fn get_enc() {
    static tmap_enc_fn fn = nullptr;
    if (!fn) {
        void* p = nullptr;
        cudaDriverEntryPointQueryResult st;
#if CUDART_VERSION >= 12050
        cudaGetDriverEntryPointByVersion("cuTensorMapEncodeTiled", &p, 12000,
                                         cudaEnableDefault, &st);
#else
        cudaGetDriverEntryPoint("cuTensorMapEncodeTiled", &p,
                                cudaEnableDefault, &st);
#endif
        fn = (tmap_enc_fn)p;
    }
    return fn;
}

static void encode_map(CUtensorMap* m, void* base, uint64_t rows,
                       uint32_t box_cols, uint32_t box_rows) {
    cuuint64_t gdim[2] = { DIMSZ, rows };
    cuuint64_t gstr[1] = { DIMSZ * 2 };
    cuuint32_t box[2]  = { box_cols, box_rows };
    cuuint32_t estr[2] = { 1, 1 };
    get_enc()(m, CU_TENSOR_MAP_DATA_TYPE_FLOAT16, 2, base,
              gdim, gstr, box, estr,
              CU_TENSOR_MAP_INTERLEAVE_NONE, CU_TENSOR_MAP_SWIZZLE_128B,
              CU_TENSOR_MAP_L2_PROMOTION_L2_128B,
              CU_TENSOR_MAP_FLOAT_OOB_FILL_NONE);
}

// ---------------------------------------------------------------------------
extern "C" void kernel_launch(void* const* d_in, const int* in_sizes, int n_in,
                              void* d_out, int out_size)
{
    const float* x_q   = (const float*)d_in[0];
    const float* x_k   = (const float*)d_in[1];
    const float* x_v   = (const float*)d_in[2];
    const float* Wq    = (const float*)d_in[3];
    const float* Wk    = (const float*)d_in[4];
    const float* Wv    = (const float*)d_in[5];
    const float* Wproj = (const float*)d_in[6];
    const float* qn_g  = (const float*)d_in[7];
    const float* qn_b  = (const float*)d_in[8];
    const float* kn_g  = (const float*)d_in[9];
    const float* kn_b  = (const float*)d_in[10];
    const float* n_g   = (const float*)d_in[11];
    const float* n_b   = (const float*)d_in[12];
    float* out = (float*)d_out;

    float *Xp;
    __half *Qh, *Kp, *Vp, *xh, *wh, *Xh;
    cudaGetSymbolAddress((void**)&Qh, g_Qh);
    cudaGetSymbolAddress((void**)&Kp, g_K);
    cudaGetSymbolAddress((void**)&Vp, g_V);
    cudaGetSymbolAddress((void**)&Xp, g_X);
    cudaGetSymbolAddress((void**)&xh, g_xh);
    cudaGetSymbolAddress((void**)&wh, g_wh);
    cudaGetSymbolAddress((void**)&Xh, g_Xh);

    static bool attr_set = false;
    if (!attr_set) {
        cudaFuncSetAttribute(gemm_qkv,
                             cudaFuncAttributeMaxDynamicSharedMemorySize, GEMM_SMEM);
        cudaFuncSetAttribute(gemm_proj,
                             cudaFuncAttributeMaxDynamicSharedMemorySize, GEMM_SMEM);
        cudaFuncSetAttribute(attn_mma,
                             cudaFuncAttributeMaxDynamicSharedMemorySize, ATTN_SMEM);
        attr_set = true;
    }

    // tensor maps (host-side compute; passed by value -> graph-capture-safe)
    CUtensorMap kmap, vmap, xmap, wmap, xhmap;
    encode_map(&kmap, Kp, NB, HDIM, 128);
    encode_map(&vmap, Vp, NB, HDIM, 128);
    encode_map(&xmap, xh, 3 * BSROWS, 64, 128);
    encode_map(&wmap, wh, 4 * DIMSZ, 64, 64);
    encode_map(&xhmap, Xh, BSROWS, 64, 128);

    // fp32 -> fp16 inputs (x_q/x_k/x_v + 4 weights)
    dim3 cvt_grid(BSROWS * DIMSZ / (256 * 8), 7);
    cvt_f2h<<<cvt_grid, 256>>>(x_q, x_k, x_v, Wq, Wk, Wv, Wproj, xh, wh);

    // fused Q/K/V projections + per-head LN (fp16 out) / V fp16 (TMA pipe)
    dim3 qkv_grid(DIMSZ / 64, BSROWS / 128, 3);
    gemm_qkv<<<qkv_grid, 256, GEMM_SMEM>>>(xmap, wmap, Qh, Kp, Vp,
                                           qn_g, qn_b, kn_g, kn_b);

    // fused attention (TMA-fed K/V pipeline)
    attn_mma<<<BSZ * NHEAD, 256, ATTN_SMEM>>>(kmap, vmap, Qh, Xp);

    // output layernorm (fp16 out) + projection (TMA pipe)
    ln_full<<<BSROWS / 8, 256>>>(Xp, Xh, n_g, n_b);
    dim3 proj_grid(DIMSZ / 64, BSROWS / 128);
    gemm_proj<<<proj_grid, 256, GEMM_SMEM>>>(xhmap, wmap, out);
}